// round 10
// baseline (speedup 1.0000x reference)
#include <cuda_runtime.h>
#include <cstdint>
#include <math.h>

#define EMBED 1024
#define NHEADS 16
#define HD 64
#define BB 2
#define SS 2048
#define BHD (BB*NHEADS)   // 32
#define MROWS (BB*SS)     // 4096
#define SCALE 0.03125f    // 1/sqrt(1024)

// Pre-rounded (tf32) copies of inputs
__device__ float g_Xr[3][(size_t)MROWS*EMBED];
__device__ float g_Wr[3][(size_t)EMBED*EMBED];
// Projected Q,K in [B,H,S,D]; V stored TRANSPOSED as [B,H,D,S]. All tf32-rounded.
__device__ float g_Q[(size_t)BB*NHEADS*SS*HD];
__device__ float g_K[(size_t)BB*NHEADS*SS*HD];
__device__ float g_V[(size_t)BB*NHEADS*SS*HD];

__device__ __forceinline__ float to_tf32(float x) {
    float r;
    asm("cvt.rna.tf32.f32 %0, %1;" : "=f"(r) : "f"(x));
    return r;
}

__device__ __forceinline__ uint32_t smem_u32(const void* p) {
    uint32_t a;
    asm("{ .reg .u64 t; cvta.to.shared.u64 t, %1; cvt.u32.u64 %0, t; }" : "=r"(a) : "l"(p));
    return a;
}

// D = A(16x8 tf32) * B(8x8 tf32) + D, f32 accum. row.col layout.
__device__ __forceinline__ void mma8(float* d, const uint32_t* a, const uint32_t* b) {
    asm volatile(
        "mma.sync.aligned.m16n8k8.row.col.f32.tf32.tf32.f32 "
        "{%0,%1,%2,%3}, {%4,%5,%6,%7}, {%8,%9}, {%0,%1,%2,%3};"
        : "+f"(d[0]), "+f"(d[1]), "+f"(d[2]), "+f"(d[3])
        : "r"(a[0]), "r"(a[1]), "r"(a[2]), "r"(a[3]), "r"(b[0]), "r"(b[1]));
}

// ldmatrix x4 (b16 view of tf32 data)
__device__ __forceinline__ void ldsm_x4(uint32_t* r, uint32_t addr) {
    asm volatile("ldmatrix.sync.aligned.m8n8.x4.shared.b16 {%0,%1,%2,%3}, [%4];"
        : "=r"(r[0]), "=r"(r[1]), "=r"(r[2]), "=r"(r[3]) : "r"(addr));
}

// cp.async helpers
__device__ __forceinline__ void cp16(uint32_t dst, const void* src) {
    asm volatile("cp.async.cg.shared.global [%0], [%1], 16;" :: "r"(dst), "l"(src));
}
__device__ __forceinline__ void cp4(uint32_t dst, const void* src) {
    asm volatile("cp.async.ca.shared.global [%0], [%1], 4;" :: "r"(dst), "l"(src));
}
#define CP_COMMIT() asm volatile("cp.async.commit_group;" ::: "memory")
#define CP_WAIT0()  asm volatile("cp.async.wait_group 0;" ::: "memory")

// ---------------------------------------------------------------------------
// Kernel 0: fused tf32 rounding of all 6 input arrays (one launch)
// ---------------------------------------------------------------------------
__global__ void __launch_bounds__(256) round_all_kernel(
    const float* __restrict__ s0, const float* __restrict__ s1, const float* __restrict__ s2,
    const float* __restrict__ s3, const float* __restrict__ s4, const float* __restrict__ s5)
{
    const int z = blockIdx.y;
    const int nx4 = MROWS * EMBED / 4;
    const int nw4 = EMBED * EMBED / 4;
    const int n4 = (z < 3) ? nx4 : nw4;
    int i = blockIdx.x * 256 + threadIdx.x;
    if (i >= n4) return;
    const float* src = (z == 0) ? s0 : (z == 1) ? s1 : (z == 2) ? s2
                     : (z == 3) ? s3 : (z == 4) ? s4 : s5;
    float* dst = (z < 3) ? g_Xr[z] : g_Wr[z - 3];
    float4 v = ((const float4*)src)[i];
    v.x = to_tf32(v.x); v.y = to_tf32(v.y);
    v.z = to_tf32(v.z); v.w = to_tf32(v.w);
    ((float4*)dst)[i] = v;
}

// ---------------------------------------------------------------------------
// Kernel 1: QKV projection  y = tf32_round(x @ W^T + b)
// Q,K -> [B,H,S,D];  V -> [B,H,D,S] (transposed).
// BM=BN=128, BK=32. 8 warps as 2x4, warp tile 64x32.
// cp.async double-buffered staging, 1 barrier/chunk.
// ---------------------------------------------------------------------------
#define PSTR 36            // 144B rows, %128=16 -> ldsm conflict-free
#define PBUF (2*128*PSTR)
#define PROJ_SMEM_BYTES (2 * PBUF * 4)   // 73728

__global__ void __launch_bounds__(256, 2) proj_kernel(
    const float* __restrict__ bq, const float* __restrict__ bk, const float* __restrict__ bv)
{
    extern __shared__ float psm[];
    const uint32_t base = smem_u32(psm);

    const int z = blockIdx.z;
    const float* x = g_Xr[z];
    const float* W = g_Wr[z];
    const float* bias = (z == 0) ? bq : (z == 1) ? bk : bv;
    float* outp = (z == 0) ? g_Q : (z == 1) ? g_K : g_V;

    const int m0 = blockIdx.y * 128;
    const int n0 = blockIdx.x * 128;
    const int tid  = threadIdx.x;
    const int wid  = tid >> 5;
    const int lane = tid & 31;
    const int g    = lane >> 2;
    const int t4   = lane & 3;
    const int wm   = (wid >> 2) * 64;
    const int wn   = (wid & 3) * 32;

    const uint32_t a_l15 = (uint32_t)(lane & 15);
    const uint32_t a_hi4 = (uint32_t)((lane >> 4) << 2);
    const uint32_t b_row = (uint32_t)(((lane >> 4) << 3) + (lane & 7));
    const uint32_t b_c4  = (uint32_t)(((lane >> 3) & 1) << 2);

#define PROJ_ISSUE(C, BUF)                                                      \
    {                                                                           \
        const int k0_ = (C) * 32;                                               \
        const uint32_t ab_ = base + (uint32_t)((BUF) * PBUF) * 4u;              \
        const uint32_t bb_ = ab_ + 128u * PSTR * 4u;                            \
        _Pragma("unroll")                                                       \
        for (int i = 0; i < 4; i++) {                                           \
            int idx = tid + i * 256;                                            \
            int r = idx >> 3, c4 = idx & 7;                                     \
            cp16(ab_ + 4u * (uint32_t)(r * PSTR + c4 * 4),                      \
                 x + (size_t)(m0 + r) * EMBED + k0_ + c4 * 4);                  \
            cp16(bb_ + 4u * (uint32_t)(r * PSTR + c4 * 4),                      \
                 W + (size_t)(n0 + r) * EMBED + k0_ + c4 * 4);                  \
        }                                                                       \
        CP_COMMIT();                                                            \
    }

    float acc[4][4][4];
    #pragma unroll
    for (int mi = 0; mi < 4; mi++)
        #pragma unroll
        for (int nj = 0; nj < 4; nj++)
            #pragma unroll
            for (int e = 0; e < 4; e++) acc[mi][nj][e] = 0.f;

    PROJ_ISSUE(0, 0);

    for (int c = 0; c < EMBED / 32; c++) {
        const int buf = c & 1;
        CP_WAIT0();
        __syncthreads();
        if (c + 1 < EMBED / 32) PROJ_ISSUE(c + 1, buf ^ 1);

        const uint32_t asb = base + (uint32_t)(buf * PBUF) * 4u;
        const uint32_t bsb = asb + 128u * PSTR * 4u;
        #pragma unroll
        for (int ks = 0; ks < 4; ks++) {
            uint32_t af[4][4], bf4[2][4];
            #pragma unroll
            for (int mi = 0; mi < 4; mi++)
                ldsm_x4(af[mi], asb + 4u * ((uint32_t)(wm + mi * 16) * PSTR + a_l15 * PSTR
                                            + (uint32_t)(ks * 8) + a_hi4));
            #pragma unroll
            for (int p = 0; p < 2; p++)
                ldsm_x4(bf4[p], bsb + 4u * ((uint32_t)(wn + p * 16) * PSTR + b_row * PSTR
                                            + (uint32_t)(ks * 8) + b_c4));
            #pragma unroll
            for (int mi = 0; mi < 4; mi++)
                #pragma unroll
                for (int nj = 0; nj < 4; nj++)
                    mma8(acc[mi][nj], af[mi], &bf4[nj >> 1][(nj & 1) * 2]);
        }
    }

    #pragma unroll
    for (int mi = 0; mi < 4; mi++) {
        int r0 = m0 + wm + mi * 16 + g;
        int r1 = r0 + 8;
        int bb0 = r0 >> 11, s0 = r0 & 2047;
        int bb1 = r1 >> 11, s1 = r1 & 2047;
        #pragma unroll
        for (int nj = 0; nj < 4; nj++) {
            int f = n0 + wn + nj * 8 + 2 * t4;
            int h = f >> 6, dd = f & 63;
            float b0 = bias[f], b1 = bias[f + 1];
            float v0 = to_tf32(acc[mi][nj][0] + b0);
            float v1 = to_tf32(acc[mi][nj][1] + b1);
            float v2 = to_tf32(acc[mi][nj][2] + b0);
            float v3 = to_tf32(acc[mi][nj][3] + b1);
            if (z == 2) {
                float* base0 = outp + (((size_t)(bb0 * NHEADS + h)) * HD + dd) * SS;
                float* base1 = outp + (((size_t)(bb1 * NHEADS + h)) * HD + dd) * SS;
                base0[s0] = v0; base0[SS + s0] = v1;
                base1[s1] = v2; base1[SS + s1] = v3;
            } else {
                float* p0 = outp + (((size_t)(bb0 * NHEADS + h)) * SS + s0) * HD + dd;
                float* p1 = outp + (((size_t)(bb1 * NHEADS + h)) * SS + s1) * HD + dd;
                *(float2*)p0 = make_float2(v0, v1);
                *(float2*)p1 = make_float2(v2, v3);
            }
        }
    }
}

// ---------------------------------------------------------------------------
// Kernel 2: attention. 128 threads (4 warps), warp tile 32 rows, k-tile 32.
// Q frags resident; V^T B-frags via ldmatrix; cp.async double buffer.
// ---------------------------------------------------------------------------
#define ASTR 68   // Qs/Ks stride (272B, %128=16)
#define VTSTR 36  // Vt stride (144B, %128=16)
#define KTILE 32

#define OFF_Q  0
#define OFF_K  (128 * ASTR)                 // 8704
#define OFF_VT (OFF_K + 2 * KTILE * ASTR)   // 13056
#define OFF_MK (OFF_VT + 2 * 64 * VTSTR)    // 17664 (ints)
#define ASM_FLOATS (OFF_MK + 2 * KTILE)     // 17728 floats = 70912 B

__global__ void __launch_bounds__(128, 2) attn_kernel(const int* __restrict__ amask,
                                                      float* __restrict__ out)
{
    extern __shared__ float sm[];
    float* Qs = sm;
    const uint32_t qsb = smem_u32(sm);

    const int tid  = threadIdx.x;
    const int wid  = tid >> 5;
    const int lane = tid & 31;
    const int g    = lane >> 2;
    const int t4   = lane & 3;
    const int wm   = wid * 32;

    const uint32_t a_l15 = (uint32_t)(lane & 15);
    const uint32_t a_hi4 = (uint32_t)((lane >> 4) << 2);
    const uint32_t b_row = (uint32_t)(((lane >> 4) << 3) + (lane & 7));
    const uint32_t b_c4  = (uint32_t)(((lane >> 3) & 1) << 2);

    const int bh = blockIdx.x;
    const int b  = bh >> 4;
    const int q0 = blockIdx.y * 128;

    const float* Qb = g_Q + (size_t)bh * SS * HD;
    const float* Kb = g_K + (size_t)bh * SS * HD;
    const float* Vb = g_V + (size_t)bh * HD * SS;   // [d][s]

    #pragma unroll
    for (int i = 0; i < 16; i++) {
        int idx = tid + i * 128;
        int r = idx >> 4, c4 = idx & 15;
        *(float4*)&Qs[r * ASTR + c4 * 4] = *(const float4*)(Qb + (size_t)(q0 + r) * HD + c4 * 4);
    }

#define ISSUE_TILE(KT, BUF)                                                        \
    {                                                                              \
        const int k0_ = (KT) * KTILE;                                              \
        const uint32_t kb_ = qsb + 4u * (uint32_t)(OFF_K  + (BUF) * KTILE * ASTR); \
        const uint32_t vb_ = qsb + 4u * (uint32_t)(OFF_VT + (BUF) * 64 * VTSTR);   \
        _Pragma("unroll")                                                          \
        for (int i = 0; i < 4; i++) {                                              \
            int idx = tid + i * 128;                                               \
            int rk = idx >> 4, ck = idx & 15;                                      \
            cp16(kb_ + 4u * (uint32_t)(rk * ASTR + ck * 4),                        \
                 Kb + (size_t)(k0_ + rk) * HD + ck * 4);                           \
            int rv = idx >> 3, cv = idx & 7;                                       \
            cp16(vb_ + 4u * (uint32_t)(rv * VTSTR + cv * 4),                       \
                 Vb + (size_t)rv * SS + k0_ + cv * 4);                             \
        }                                                                          \
        if (tid < KTILE)                                                           \
            cp4(qsb + 4u * (uint32_t)(OFF_MK + (BUF) * KTILE + tid),               \
                amask + (size_t)b * SS + k0_ + tid);                               \
        CP_COMMIT();                                                               \
    }

    ISSUE_TILE(0, 0);

    __syncthreads();
    uint32_t qf[2][8][4];
    #pragma unroll
    for (int mi = 0; mi < 2; mi++)
        #pragma unroll
        for (int ks = 0; ks < 8; ks++)
            ldsm_x4(qf[mi][ks], qsb + 4u * ((uint32_t)(wm + mi * 16 + (int)a_l15) * ASTR
                                            + (uint32_t)(ks * 8) + a_hi4));

    float oacc[2][8][4];
    #pragma unroll
    for (int mi = 0; mi < 2; mi++)
        #pragma unroll
        for (int nj = 0; nj < 8; nj++)
            #pragma unroll
            for (int e = 0; e < 4; e++) oacc[mi][nj][e] = 0.f;
    float lrA[2] = {0.f, 0.f}, lrB[2] = {0.f, 0.f};

    const int srcA = (lane & 28) | (t4 >> 1);
    const int srcB = srcA + 2;
    const bool odd = (t4 & 1) != 0;

    for (int kt = 0; kt < SS / KTILE; kt++) {
        const int buf = kt & 1;

        CP_WAIT0();
        __syncthreads();
        if (kt + 1 < SS / KTILE) ISSUE_TILE(kt + 1, buf ^ 1);

        const uint32_t ksb = qsb + 4u * (uint32_t)(OFF_K  + buf * KTILE * ASTR)
                           + 4u * (b_row * ASTR + b_c4);
        const uint32_t vsb = qsb + 4u * (uint32_t)(OFF_VT + buf * 64 * VTSTR)
                           + 4u * (b_row * VTSTR + b_c4);
        const int* mki = (const int*)(sm + OFF_MK) + buf * KTILE;

        // MMA1: S[32x32]
        float sa[2][4][4];
        #pragma unroll
        for (int mi = 0; mi < 2; mi++)
            #pragma unroll
            for (int nj = 0; nj < 4; nj++)
                #pragma unroll
                for (int e = 0; e < 4; e++) sa[mi][nj][e] = 0.f;

        #pragma unroll
        for (int ks = 0; ks < 8; ks++) {
            uint32_t bq[2][4];
            #pragma unroll
            for (int p = 0; p < 2; p++)
                ldsm_x4(bq[p], ksb + 4u * (uint32_t)(p * 16 * ASTR + ks * 8));
            #pragma unroll
            for (int mi = 0; mi < 2; mi++)
                #pragma unroll
                for (int nj = 0; nj < 4; nj++)
                    mma8(sa[mi][nj], qf[mi][ks], &bq[nj >> 1][(nj & 1) * 2]);
        }

        // softmax piece
        #pragma unroll
        for (int nj = 0; nj < 4; nj++) {
            bool m0 = mki[nj * 8 + 2 * t4] != 0;
            bool m1 = mki[nj * 8 + 2 * t4 + 1] != 0;
            #pragma unroll
            for (int mi = 0; mi < 2; mi++) {
                float p0 = m0 ? __expf(sa[mi][nj][0] * SCALE) : 0.f;
                float p1 = m1 ? __expf(sa[mi][nj][1] * SCALE) : 0.f;
                float p2 = m0 ? __expf(sa[mi][nj][2] * SCALE) : 0.f;
                float p3 = m1 ? __expf(sa[mi][nj][3] * SCALE) : 0.f;
                sa[mi][nj][0] = p0; sa[mi][nj][1] = p1;
                sa[mi][nj][2] = p2; sa[mi][nj][3] = p3;
                lrA[mi] += p0 + p1;
                lrB[mi] += p2 + p3;
            }
        }

        // MMA2: O[32x64] += P[32x32] V
        #pragma unroll
        for (int ks = 0; ks < 4; ks++) {
            uint32_t pa[2][4];
            #pragma unroll
            for (int mi = 0; mi < 2; mi++) {
                float v0 = __shfl_sync(0xFFFFFFFFu, sa[mi][ks][0], srcA);
                float v1 = __shfl_sync(0xFFFFFFFFu, sa[mi][ks][1], srcA);
                float v2 = __shfl_sync(0xFFFFFFFFu, sa[mi][ks][2], srcA);
                float v3 = __shfl_sync(0xFFFFFFFFu, sa[mi][ks][3], srcA);
                float w0 = __shfl_sync(0xFFFFFFFFu, sa[mi][ks][0], srcB);
                float w1 = __shfl_sync(0xFFFFFFFFu, sa[mi][ks][1], srcB);
                float w2 = __shfl_sync(0xFFFFFFFFu, sa[mi][ks][2], srcB);
                float w3 = __shfl_sync(0xFFFFFFFFu, sa[mi][ks][3], srcB);
                pa[mi][0] = __float_as_uint(to_tf32(odd ? v1 : v0));
                pa[mi][1] = __float_as_uint(to_tf32(odd ? v3 : v2));
                pa[mi][2] = __float_as_uint(to_tf32(odd ? w1 : w0));
                pa[mi][3] = __float_as_uint(to_tf32(odd ? w3 : w2));
            }
            uint32_t bv[4][4];
            #pragma unroll
            for (int p = 0; p < 4; p++)
                ldsm_x4(bv[p], vsb + 4u * (uint32_t)(p * 16 * VTSTR + ks * 8));
            #pragma unroll
            for (int mi = 0; mi < 2; mi++)
                #pragma unroll
                for (int nj = 0; nj < 8; nj++)
                    mma8(oacc[mi][nj], pa[mi], &bv[nj >> 1][(nj & 1) * 2]);
        }
    }

    #pragma unroll
    for (int mi = 0; mi < 2; mi++) {
        lrA[mi] += __shfl_xor_sync(0xFFFFFFFFu, lrA[mi], 1);
        lrA[mi] += __shfl_xor_sync(0xFFFFFFFFu, lrA[mi], 2);
        lrB[mi] += __shfl_xor_sync(0xFFFFFFFFu, lrB[mi], 1);
        lrB[mi] += __shfl_xor_sync(0xFFFFFFFFu, lrB[mi], 2);
    }

    #pragma unroll
    for (int mi = 0; mi < 2; mi++) {
        int r0 = wm + mi * 16 + g;
        int r1 = r0 + 8;
        float il0 = 1.f / lrA[mi];
        float il1 = 1.f / lrB[mi];
        #pragma unroll
        for (int nj = 0; nj < 8; nj++) {
            int c0 = nj * 8 + 2 * t4;
            float* p0 = out + ((size_t)bh * SS + q0 + r0) * HD + c0;
            float* p1 = out + ((size_t)bh * SS + q0 + r1) * HD + c0;
            *(float2*)p0 = make_float2(oacc[mi][nj][0] * il0, oacc[mi][nj][1] * il0);
            *(float2*)p1 = make_float2(oacc[mi][nj][2] * il1, oacc[mi][nj][3] * il1);
        }
    }
}

// ---------------------------------------------------------------------------
extern "C" void kernel_launch(void* const* d_in, const int* in_sizes, int n_in,
                              void* d_out, int out_size)
{
    (void)in_sizes; (void)n_in; (void)out_size;
    const float* q  = (const float*)d_in[0];
    const float* k  = (const float*)d_in[1];
    const float* v  = (const float*)d_in[2];
    const int*   am = (const int*)  d_in[3];
    const float* Wq = (const float*)d_in[4];
    const float* bq = (const float*)d_in[5];
    const float* Wk = (const float*)d_in[6];
    const float* bk = (const float*)d_in[7];
    const float* Wv = (const float*)d_in[8];
    const float* bv = (const float*)d_in[9];

    static int attr_set = 0;
    if (!attr_set) {
        cudaFuncSetAttribute(attn_kernel, cudaFuncAttributeMaxDynamicSharedMemorySize,
                             ASM_FLOATS * (int)sizeof(float));
        cudaFuncSetAttribute(proj_kernel, cudaFuncAttributeMaxDynamicSharedMemorySize,
                             PROJ_SMEM_BYTES);
        attr_set = 1;
    }

    const int nx4 = MROWS * EMBED / 4;
    dim3 rgrid((nx4 + 255) / 256, 6);
    round_all_kernel<<<rgrid, 256>>>(q, k, v, Wq, Wk, Wv);

    dim3 pgrid(EMBED / 128, MROWS / 128, 3);
    proj_kernel<<<pgrid, 256, PROJ_SMEM_BYTES>>>(bq, bk, bv);

    dim3 agrid(BHD, SS / 128);
    attn_kernel<<<agrid, 128, ASM_FLOATS * sizeof(float)>>>(am, (float*)d_out);
}

// round 11
// speedup vs baseline: 1.5048x; 1.5048x over previous
#include <cuda_runtime.h>
#include <cstdint>
#include <math.h>

#define EMBED 1024
#define NHEADS 16
#define HD 64
#define BB 2
#define SS 2048
#define BHD (BB*NHEADS)   // 32
#define MROWS (BB*SS)     // 4096
#define SCALE 0.03125f    // 1/sqrt(1024)

// Pre-rounded (tf32) copies of inputs
__device__ float g_Xr[3][(size_t)MROWS*EMBED];
__device__ float g_Wr[3][(size_t)EMBED*EMBED];
// Projected Q,K in [B,H,S,D]; V stored TRANSPOSED as [B,H,D,S]. All tf32-rounded.
__device__ float g_Q[(size_t)BB*NHEADS*SS*HD];
__device__ float g_K[(size_t)BB*NHEADS*SS*HD];
__device__ float g_V[(size_t)BB*NHEADS*SS*HD];

__device__ __forceinline__ float to_tf32(float x) {
    float r;
    asm("cvt.rna.tf32.f32 %0, %1;" : "=f"(r) : "f"(x));
    return r;
}

__device__ __forceinline__ uint32_t smem_u32(const void* p) {
    uint32_t a;
    asm("{ .reg .u64 t; cvta.to.shared.u64 t, %1; cvt.u32.u64 %0, t; }" : "=r"(a) : "l"(p));
    return a;
}

// D = A(16x8 tf32) * B(8x8 tf32) + D, f32 accum. row.col layout.
__device__ __forceinline__ void mma8(float* d, const uint32_t* a, const uint32_t* b) {
    asm volatile(
        "mma.sync.aligned.m16n8k8.row.col.f32.tf32.tf32.f32 "
        "{%0,%1,%2,%3}, {%4,%5,%6,%7}, {%8,%9}, {%0,%1,%2,%3};"
        : "+f"(d[0]), "+f"(d[1]), "+f"(d[2]), "+f"(d[3])
        : "r"(a[0]), "r"(a[1]), "r"(a[2]), "r"(a[3]), "r"(b[0]), "r"(b[1]));
}

// ldmatrix x4 (b16 view of tf32 data)
__device__ __forceinline__ void ldsm_x4(uint32_t* r, uint32_t addr) {
    asm volatile("ldmatrix.sync.aligned.m8n8.x4.shared.b16 {%0,%1,%2,%3}, [%4];"
        : "=r"(r[0]), "=r"(r[1]), "=r"(r[2]), "=r"(r[3]) : "r"(addr));
}

// cp.async helpers
__device__ __forceinline__ void cp16(uint32_t dst, const void* src) {
    asm volatile("cp.async.cg.shared.global [%0], [%1], 16;" :: "r"(dst), "l"(src));
}
__device__ __forceinline__ void cp4(uint32_t dst, const void* src) {
    asm volatile("cp.async.ca.shared.global [%0], [%1], 4;" :: "r"(dst), "l"(src));
}
#define CP_COMMIT() asm volatile("cp.async.commit_group;" ::: "memory")
#define CP_WAIT0()  asm volatile("cp.async.wait_group 0;" ::: "memory")

// ---------------------------------------------------------------------------
// Kernel 0: fused tf32 rounding of all 6 input arrays (one launch)
// ---------------------------------------------------------------------------
__global__ void __launch_bounds__(256) round_all_kernel(
    const float* __restrict__ s0, const float* __restrict__ s1, const float* __restrict__ s2,
    const float* __restrict__ s3, const float* __restrict__ s4, const float* __restrict__ s5)
{
    const int z = blockIdx.y;
    const int nx4 = MROWS * EMBED / 4;
    const int nw4 = EMBED * EMBED / 4;
    const int n4 = (z < 3) ? nx4 : nw4;
    int i = blockIdx.x * 256 + threadIdx.x;
    if (i >= n4) return;
    const float* src = (z == 0) ? s0 : (z == 1) ? s1 : (z == 2) ? s2
                     : (z == 3) ? s3 : (z == 4) ? s4 : s5;
    float* dst = (z < 3) ? g_Xr[z] : g_Wr[z - 3];
    float4 v = ((const float4*)src)[i];
    v.x = to_tf32(v.x); v.y = to_tf32(v.y);
    v.z = to_tf32(v.z); v.w = to_tf32(v.w);
    ((float4*)dst)[i] = v;
}

// ---------------------------------------------------------------------------
// Kernel 1: QKV projection  y = tf32_round(x @ W^T + b)
// Q,K -> [B,H,S,D];  V -> [B,H,D,S] (transposed).
// BM=BN=128, BK=32. 8 warps as 2x4, warp tile 64x32.
// cp.async double-buffered staging, 1 barrier/chunk.
// ---------------------------------------------------------------------------
#define PSTR 36            // 144B rows, %128=16 -> ldsm conflict-free
#define PBUF (2*128*PSTR)
#define PROJ_SMEM_BYTES (2 * PBUF * 4)   // 73728

__global__ void __launch_bounds__(256, 2) proj_kernel(
    const float* __restrict__ bq, const float* __restrict__ bk, const float* __restrict__ bv)
{
    extern __shared__ float psm[];
    const uint32_t base = smem_u32(psm);

    const int z = blockIdx.z;
    const float* x = g_Xr[z];
    const float* W = g_Wr[z];
    const float* bias = (z == 0) ? bq : (z == 1) ? bk : bv;
    float* outp = (z == 0) ? g_Q : (z == 1) ? g_K : g_V;

    const int m0 = blockIdx.y * 128;
    const int n0 = blockIdx.x * 128;
    const int tid  = threadIdx.x;
    const int wid  = tid >> 5;
    const int lane = tid & 31;
    const int g    = lane >> 2;
    const int t4   = lane & 3;
    const int wm   = (wid >> 2) * 64;
    const int wn   = (wid & 3) * 32;

    const uint32_t a_l15 = (uint32_t)(lane & 15);
    const uint32_t a_hi4 = (uint32_t)((lane >> 4) << 2);
    const uint32_t b_row = (uint32_t)(((lane >> 4) << 3) + (lane & 7));
    const uint32_t b_c4  = (uint32_t)(((lane >> 3) & 1) << 2);

#define PROJ_ISSUE(C, BUF)                                                      \
    {                                                                           \
        const int k0_ = (C) * 32;                                               \
        const uint32_t ab_ = base + (uint32_t)((BUF) * PBUF) * 4u;              \
        const uint32_t bb_ = ab_ + 128u * PSTR * 4u;                            \
        _Pragma("unroll")                                                       \
        for (int i = 0; i < 4; i++) {                                           \
            int idx = tid + i * 256;                                            \
            int r = idx >> 3, c4 = idx & 7;                                     \
            cp16(ab_ + 4u * (uint32_t)(r * PSTR + c4 * 4),                      \
                 x + (size_t)(m0 + r) * EMBED + k0_ + c4 * 4);                  \
            cp16(bb_ + 4u * (uint32_t)(r * PSTR + c4 * 4),                      \
                 W + (size_t)(n0 + r) * EMBED + k0_ + c4 * 4);                  \
        }                                                                       \
        CP_COMMIT();                                                            \
    }

    float acc[4][4][4];
    #pragma unroll
    for (int mi = 0; mi < 4; mi++)
        #pragma unroll
        for (int nj = 0; nj < 4; nj++)
            #pragma unroll
            for (int e = 0; e < 4; e++) acc[mi][nj][e] = 0.f;

    PROJ_ISSUE(0, 0);

    for (int c = 0; c < EMBED / 32; c++) {
        const int buf = c & 1;
        CP_WAIT0();
        __syncthreads();
        if (c + 1 < EMBED / 32) PROJ_ISSUE(c + 1, buf ^ 1);

        const uint32_t asb = base + (uint32_t)(buf * PBUF) * 4u;
        const uint32_t bsb = asb + 128u * PSTR * 4u;
        #pragma unroll
        for (int ks = 0; ks < 4; ks++) {
            uint32_t af[4][4], bf4[2][4];
            #pragma unroll
            for (int mi = 0; mi < 4; mi++)
                ldsm_x4(af[mi], asb + 4u * ((uint32_t)(wm + mi * 16) * PSTR + a_l15 * PSTR
                                            + (uint32_t)(ks * 8) + a_hi4));
            #pragma unroll
            for (int p = 0; p < 2; p++)
                ldsm_x4(bf4[p], bsb + 4u * ((uint32_t)(wn + p * 16) * PSTR + b_row * PSTR
                                            + (uint32_t)(ks * 8) + b_c4));
            #pragma unroll
            for (int mi = 0; mi < 4; mi++)
                #pragma unroll
                for (int nj = 0; nj < 4; nj++)
                    mma8(acc[mi][nj], af[mi], &bf4[nj >> 1][(nj & 1) * 2]);
        }
    }

    #pragma unroll
    for (int mi = 0; mi < 4; mi++) {
        int r0 = m0 + wm + mi * 16 + g;
        int r1 = r0 + 8;
        int bb0 = r0 >> 11, s0 = r0 & 2047;
        int bb1 = r1 >> 11, s1 = r1 & 2047;
        #pragma unroll
        for (int nj = 0; nj < 4; nj++) {
            int f = n0 + wn + nj * 8 + 2 * t4;
            int h = f >> 6, dd = f & 63;
            float b0 = bias[f], b1 = bias[f + 1];
            float v0 = to_tf32(acc[mi][nj][0] + b0);
            float v1 = to_tf32(acc[mi][nj][1] + b1);
            float v2 = to_tf32(acc[mi][nj][2] + b0);
            float v3 = to_tf32(acc[mi][nj][3] + b1);
            if (z == 2) {
                // V transposed: [B,H,D,S]
                float* base0 = outp + (((size_t)(bb0 * NHEADS + h)) * HD + dd) * SS;
                float* base1 = outp + (((size_t)(bb1 * NHEADS + h)) * HD + dd) * SS;
                base0[s0] = v0; base0[SS + s0] = v1;
                base1[s1] = v2; base1[SS + s1] = v3;
            } else {
                float* p0 = outp + (((size_t)(bb0 * NHEADS + h)) * SS + s0) * HD + dd;
                float* p1 = outp + (((size_t)(bb1 * NHEADS + h)) * SS + s1) * HD + dd;
                *(float2*)p0 = make_float2(v0, v1);
                *(float2*)p1 = make_float2(v2, v3);
            }
        }
    }
}

// ---------------------------------------------------------------------------
// Kernel 2: attention. 128 threads (4 warps), warp tile 32 rows, k-tile 64.
// R8 structure (proven 268us) + V^T ldmatrix B-frags in MMA2 (R9's win):
// Q frags resident; cp.async double buffer; 1 barrier/tile; row sums in regs.
// ---------------------------------------------------------------------------
#define ASTR 68   // Qs/Ks/Vt stride (272B, %128=16: ldsm conflict-free)

#define OFF_Q  0
#define OFF_K  (128 * ASTR)              // 8704
#define OFF_VT (OFF_K + 2 * 64 * ASTR)   // 17408
#define OFF_MK (OFF_VT + 2 * 64 * ASTR)  // 26112 (ints)
#define ASM_FLOATS (OFF_MK + 128)        // 26240 floats = 104960 B

__global__ void __launch_bounds__(128, 2) attn_kernel(const int* __restrict__ amask,
                                                      float* __restrict__ out)
{
    extern __shared__ float sm[];
    float* Qs = sm;
    const uint32_t qsb = smem_u32(sm);

    const int tid  = threadIdx.x;
    const int wid  = tid >> 5;
    const int lane = tid & 31;
    const int g    = lane >> 2;
    const int t4   = lane & 3;
    const int wm   = wid * 32;

    const uint32_t a_l15 = (uint32_t)(lane & 15);
    const uint32_t a_hi4 = (uint32_t)((lane >> 4) << 2);
    const uint32_t b_row = (uint32_t)(((lane >> 4) << 3) + (lane & 7));
    const uint32_t b_c4  = (uint32_t)(((lane >> 3) & 1) << 2);

    const int bh = blockIdx.x;
    const int b  = bh >> 4;
    const int q0 = blockIdx.y * 128;

    const float* Qb = g_Q + (size_t)bh * SS * HD;
    const float* Kb = g_K + (size_t)bh * SS * HD;
    const float* Vb = g_V + (size_t)bh * HD * SS;   // transposed [d][s]

    // ---- stage Q tile [128x64] (persistent; pre-rounded) ----
    #pragma unroll
    for (int i = 0; i < 16; i++) {
        int idx = tid + i * 128;
        int r = idx >> 4, c4 = idx & 15;
        *(float4*)&Qs[r * ASTR + c4 * 4] = *(const float4*)(Qb + (size_t)(q0 + r) * HD + c4 * 4);
    }

    // issue tile KT's K (64 keys x 64 dims) + V^T (64 dims x 64 keys) + mask
#define ISSUE_TILE(KT, BUF)                                                     \
    {                                                                           \
        const int k0_ = (KT) * 64;                                              \
        const uint32_t kb_ = qsb + 4u * (uint32_t)(OFF_K  + (BUF) * 64 * ASTR); \
        const uint32_t vb_ = qsb + 4u * (uint32_t)(OFF_VT + (BUF) * 64 * ASTR); \
        _Pragma("unroll")                                                       \
        for (int i = 0; i < 8; i++) {                                           \
            int idx = tid + i * 128;                                            \
            int r = idx >> 4, c4 = idx & 15;                                    \
            cp16(kb_ + 4u * (uint32_t)(r * ASTR + c4 * 4),                      \
                 Kb + (size_t)(k0_ + r) * HD + c4 * 4);                         \
            cp16(vb_ + 4u * (uint32_t)(r * ASTR + c4 * 4),                      \
                 Vb + (size_t)r * SS + k0_ + c4 * 4);                           \
        }                                                                       \
        if (tid < 64)                                                           \
            cp4(qsb + 4u * (uint32_t)(OFF_MK + (BUF) * 64 + tid),               \
                amask + (size_t)b * SS + k0_ + tid);                            \
        CP_COMMIT();                                                            \
    }

    ISSUE_TILE(0, 0);

    // ---- resident Q fragments ----
    __syncthreads();
    uint32_t qf[2][8][4];
    #pragma unroll
    for (int mi = 0; mi < 2; mi++)
        #pragma unroll
        for (int ks = 0; ks < 8; ks++)
            ldsm_x4(qf[mi][ks], qsb + 4u * ((uint32_t)(wm + mi * 16 + (int)a_l15) * ASTR
                                            + (uint32_t)(ks * 8) + a_hi4));

    float oacc[2][8][4];
    #pragma unroll
    for (int mi = 0; mi < 2; mi++)
        #pragma unroll
        for (int nj = 0; nj < 8; nj++)
            #pragma unroll
            for (int e = 0; e < 4; e++) oacc[mi][nj][e] = 0.f;
    float lrA[2] = {0.f, 0.f}, lrB[2] = {0.f, 0.f};

    const int srcA = (lane & 28) | (t4 >> 1);
    const int srcB = srcA + 2;
    const bool odd = (t4 & 1) != 0;

    for (int kt = 0; kt < SS / 64; kt++) {
        const int buf = kt & 1;

        CP_WAIT0();        // this thread's copies for tile kt complete
        __syncthreads();   // all copies visible; all warps past compute(kt-1)

        if (kt + 1 < SS / 64) ISSUE_TILE(kt + 1, buf ^ 1);

        const uint32_t ksb = qsb + 4u * (uint32_t)(OFF_K  + buf * 64 * ASTR)
                           + 4u * (b_row * ASTR + b_c4);
        const uint32_t vsb = qsb + 4u * (uint32_t)(OFF_VT + buf * 64 * ASTR)
                           + 4u * (b_row * ASTR + b_c4);
        const int* mki = (const int*)(sm + OFF_MK) + buf * 64;

        // ---- MMA1: S[32x64] = Q K^T ----
        float sa[2][8][4];
        #pragma unroll
        for (int mi = 0; mi < 2; mi++)
            #pragma unroll
            for (int nj = 0; nj < 8; nj++)
                #pragma unroll
                for (int e = 0; e < 4; e++) sa[mi][nj][e] = 0.f;

        #pragma unroll
        for (int ks = 0; ks < 8; ks++) {
            uint32_t bq[4][4];
            #pragma unroll
            for (int p = 0; p < 4; p++)
                ldsm_x4(bq[p], ksb + 4u * (uint32_t)(p * 16 * ASTR + ks * 8));
            #pragma unroll
            for (int mi = 0; mi < 2; mi++)
                #pragma unroll
                for (int nj = 0; nj < 8; nj++)
                    mma8(sa[mi][nj], qf[mi][ks], &bq[nj >> 1][(nj & 1) * 2]);
        }

        // ---- softmax piece: p = mask ? exp(s/32) : 0; row sums in regs ----
        #pragma unroll
        for (int nj = 0; nj < 8; nj++) {
            bool m0 = mki[nj * 8 + 2 * t4] != 0;
            bool m1 = mki[nj * 8 + 2 * t4 + 1] != 0;
            #pragma unroll
            for (int mi = 0; mi < 2; mi++) {
                float p0 = m0 ? __expf(sa[mi][nj][0] * SCALE) : 0.f;
                float p1 = m1 ? __expf(sa[mi][nj][1] * SCALE) : 0.f;
                float p2 = m0 ? __expf(sa[mi][nj][2] * SCALE) : 0.f;
                float p3 = m1 ? __expf(sa[mi][nj][3] * SCALE) : 0.f;
                sa[mi][nj][0] = p0; sa[mi][nj][1] = p1;
                sa[mi][nj][2] = p2; sa[mi][nj][3] = p3;
                lrA[mi] += p0 + p1;
                lrB[mi] += p2 + p3;
            }
        }

        // ---- MMA2: O[32x64] += P[32x64] V  (A via shfl, B = V^T ldmatrix) ----
        #pragma unroll
        for (int ks = 0; ks < 8; ks++) {
            uint32_t pa[2][4];
            #pragma unroll
            for (int mi = 0; mi < 2; mi++) {
                float v0 = __shfl_sync(0xFFFFFFFFu, sa[mi][ks][0], srcA);
                float v1 = __shfl_sync(0xFFFFFFFFu, sa[mi][ks][1], srcA);
                float v2 = __shfl_sync(0xFFFFFFFFu, sa[mi][ks][2], srcA);
                float v3 = __shfl_sync(0xFFFFFFFFu, sa[mi][ks][3], srcA);
                float w0 = __shfl_sync(0xFFFFFFFFu, sa[mi][ks][0], srcB);
                float w1 = __shfl_sync(0xFFFFFFFFu, sa[mi][ks][1], srcB);
                float w2 = __shfl_sync(0xFFFFFFFFu, sa[mi][ks][2], srcB);
                float w3 = __shfl_sync(0xFFFFFFFFu, sa[mi][ks][3], srcB);
                pa[mi][0] = __float_as_uint(to_tf32(odd ? v1 : v0));
                pa[mi][1] = __float_as_uint(to_tf32(odd ? v3 : v2));
                pa[mi][2] = __float_as_uint(to_tf32(odd ? w1 : w0));
                pa[mi][3] = __float_as_uint(to_tf32(odd ? w3 : w2));
            }
            uint32_t bv[4][4];
            #pragma unroll
            for (int p = 0; p < 4; p++)   // 64 dims = 4 x (16-row ldsm pair)
                ldsm_x4(bv[p], vsb + 4u * (uint32_t)(p * 16 * ASTR + ks * 8));
            #pragma unroll
            for (int mi = 0; mi < 2; mi++)
                #pragma unroll
                for (int nj = 0; nj < 8; nj++)
                    mma8(oacc[mi][nj], pa[mi], &bv[nj >> 1][(nj & 1) * 2]);
        }
    }

    // ---- reduce row sums across quad, normalize, store ----
    #pragma unroll
    for (int mi = 0; mi < 2; mi++) {
        lrA[mi] += __shfl_xor_sync(0xFFFFFFFFu, lrA[mi], 1);
        lrA[mi] += __shfl_xor_sync(0xFFFFFFFFu, lrA[mi], 2);
        lrB[mi] += __shfl_xor_sync(0xFFFFFFFFu, lrB[mi], 1);
        lrB[mi] += __shfl_xor_sync(0xFFFFFFFFu, lrB[mi], 2);
    }

    #pragma unroll
    for (int mi = 0; mi < 2; mi++) {
        int r0 = wm + mi * 16 + g;
        int r1 = r0 + 8;
        float il0 = 1.f / lrA[mi];
        float il1 = 1.f / lrB[mi];
        #pragma unroll
        for (int nj = 0; nj < 8; nj++) {
            int c0 = nj * 8 + 2 * t4;
            float* p0 = out + ((size_t)bh * SS + q0 + r0) * HD + c0;
            float* p1 = out + ((size_t)bh * SS + q0 + r1) * HD + c0;
            *(float2*)p0 = make_float2(oacc[mi][nj][0] * il0, oacc[mi][nj][1] * il0);
            *(float2*)p1 = make_float2(oacc[mi][nj][2] * il1, oacc[mi][nj][3] * il1);
        }
    }
}

// ---------------------------------------------------------------------------
extern "C" void kernel_launch(void* const* d_in, const int* in_sizes, int n_in,
                              void* d_out, int out_size)
{
    (void)in_sizes; (void)n_in; (void)out_size;
    const float* q  = (const float*)d_in[0];
    const float* k  = (const float*)d_in[1];
    const float* v  = (const float*)d_in[2];
    const int*   am = (const int*)  d_in[3];
    const float* Wq = (const float*)d_in[4];
    const float* bq = (const float*)d_in[5];
    const float* Wk = (const float*)d_in[6];
    const float* bk = (const float*)d_in[7];
    const float* Wv = (const float*)d_in[8];
    const float* bv = (const float*)d_in[9];

    static int attr_set = 0;
    if (!attr_set) {
        cudaFuncSetAttribute(attn_kernel, cudaFuncAttributeMaxDynamicSharedMemorySize,
                             ASM_FLOATS * (int)sizeof(float));
        cudaFuncSetAttribute(proj_kernel, cudaFuncAttributeMaxDynamicSharedMemorySize,
                             PROJ_SMEM_BYTES);
        attr_set = 1;
    }

    const int nx4 = MROWS * EMBED / 4;
    dim3 rgrid((nx4 + 255) / 256, 6);
    round_all_kernel<<<rgrid, 256>>>(q, k, v, Wq, Wk, Wv);

    dim3 pgrid(EMBED / 128, MROWS / 128, 3);
    proj_kernel<<<pgrid, 256, PROJ_SMEM_BYTES>>>(bq, bk, bv);

    dim3 agrid(BHD, SS / 128);
    attn_kernel<<<agrid, 128, ASM_FLOATS * sizeof(float)>>>(am, (float*)d_out);
}

// round 12
// speedup vs baseline: 1.5093x; 1.0030x over previous
#include <cuda_runtime.h>
#include <cstdint>
#include <math.h>

#define EMBED 1024
#define NHEADS 16
#define HD 64
#define BB 2
#define SS 2048
#define BHD (BB*NHEADS)   // 32
#define MROWS (BB*SS)     // 4096
#define SCALE 0.03125f    // 1/sqrt(1024)

// Pre-rounded (tf32) copies of inputs
__device__ float g_Xr[3][(size_t)MROWS*EMBED];
__device__ float g_Wr[3][(size_t)EMBED*EMBED];
// Projected Q,K in [B,H,S,D]; V stored TRANSPOSED as [B,H,D,S]. All tf32-rounded.
__device__ float g_Q[(size_t)BB*NHEADS*SS*HD];
__device__ float g_K[(size_t)BB*NHEADS*SS*HD];
__device__ float g_V[(size_t)BB*NHEADS*SS*HD];

__device__ __forceinline__ float to_tf32(float x) {
    float r;
    asm("cvt.rna.tf32.f32 %0, %1;" : "=f"(r) : "f"(x));
    return r;
}

__device__ __forceinline__ uint32_t smem_u32(const void* p) {
    uint32_t a;
    asm("{ .reg .u64 t; cvta.to.shared.u64 t, %1; cvt.u32.u64 %0, t; }" : "=r"(a) : "l"(p));
    return a;
}

// D = A(16x8 tf32) * B(8x8 tf32) + D, f32 accum. row.col layout.
__device__ __forceinline__ void mma8(float* d, const uint32_t* a, const uint32_t* b) {
    asm volatile(
        "mma.sync.aligned.m16n8k8.row.col.f32.tf32.tf32.f32 "
        "{%0,%1,%2,%3}, {%4,%5,%6,%7}, {%8,%9}, {%0,%1,%2,%3};"
        : "+f"(d[0]), "+f"(d[1]), "+f"(d[2]), "+f"(d[3])
        : "r"(a[0]), "r"(a[1]), "r"(a[2]), "r"(a[3]), "r"(b[0]), "r"(b[1]));
}

// ldmatrix x4 (b16 view of tf32 data)
__device__ __forceinline__ void ldsm_x4(uint32_t* r, uint32_t addr) {
    asm volatile("ldmatrix.sync.aligned.m8n8.x4.shared.b16 {%0,%1,%2,%3}, [%4];"
        : "=r"(r[0]), "=r"(r[1]), "=r"(r[2]), "=r"(r[3]) : "r"(addr));
}

// cp.async helpers
__device__ __forceinline__ void cp16(uint32_t dst, const void* src) {
    asm volatile("cp.async.cg.shared.global [%0], [%1], 16;" :: "r"(dst), "l"(src));
}
__device__ __forceinline__ void cp4(uint32_t dst, const void* src) {
    asm volatile("cp.async.ca.shared.global [%0], [%1], 4;" :: "r"(dst), "l"(src));
}
#define CP_COMMIT() asm volatile("cp.async.commit_group;" ::: "memory")
#define CP_WAIT0()  asm volatile("cp.async.wait_group 0;" ::: "memory")

// ---------------------------------------------------------------------------
// Kernel 0: fused tf32 rounding of all 6 input arrays (one launch)
// ---------------------------------------------------------------------------
__global__ void __launch_bounds__(256) round_all_kernel(
    const float* __restrict__ s0, const float* __restrict__ s1, const float* __restrict__ s2,
    const float* __restrict__ s3, const float* __restrict__ s4, const float* __restrict__ s5)
{
    const int z = blockIdx.y;
    const int nx4 = MROWS * EMBED / 4;
    const int nw4 = EMBED * EMBED / 4;
    const int n4 = (z < 3) ? nx4 : nw4;
    int i = blockIdx.x * 256 + threadIdx.x;
    if (i >= n4) return;
    const float* src = (z == 0) ? s0 : (z == 1) ? s1 : (z == 2) ? s2
                     : (z == 3) ? s3 : (z == 4) ? s4 : s5;
    float* dst = (z < 3) ? g_Xr[z] : g_Wr[z - 3];
    float4 v = ((const float4*)src)[i];
    v.x = to_tf32(v.x); v.y = to_tf32(v.y);
    v.z = to_tf32(v.z); v.w = to_tf32(v.w);
    ((float4*)dst)[i] = v;
}

// ---------------------------------------------------------------------------
// Kernel 1: QKV projection  y = tf32_round(x @ W^T + b)
// Q,K -> [B,H,S,D];  V -> [B,H,D,S] (transposed).
// BM=BN=128, BK=32. 8 warps as 2x4, warp tile 64x32.
// cp.async double-buffered staging, 1 barrier/chunk.
// ---------------------------------------------------------------------------
#define PSTR 36            // 144B rows, %128=16 -> ldsm conflict-free
#define PBUF (2*128*PSTR)
#define PROJ_SMEM_BYTES (2 * PBUF * 4)   // 73728

__global__ void __launch_bounds__(256, 2) proj_kernel(
    const float* __restrict__ bq, const float* __restrict__ bk, const float* __restrict__ bv)
{
    extern __shared__ float psm[];
    const uint32_t base = smem_u32(psm);

    const int z = blockIdx.z;
    const float* x = g_Xr[z];
    const float* W = g_Wr[z];
    const float* bias = (z == 0) ? bq : (z == 1) ? bk : bv;
    float* outp = (z == 0) ? g_Q : (z == 1) ? g_K : g_V;

    const int m0 = blockIdx.y * 128;
    const int n0 = blockIdx.x * 128;
    const int tid  = threadIdx.x;
    const int wid  = tid >> 5;
    const int lane = tid & 31;
    const int g    = lane >> 2;
    const int t4   = lane & 3;
    const int wm   = (wid >> 2) * 64;
    const int wn   = (wid & 3) * 32;

    const uint32_t a_l15 = (uint32_t)(lane & 15);
    const uint32_t a_hi4 = (uint32_t)((lane >> 4) << 2);
    const uint32_t b_row = (uint32_t)(((lane >> 4) << 3) + (lane & 7));
    const uint32_t b_c4  = (uint32_t)(((lane >> 3) & 1) << 2);

#define PROJ_ISSUE(C, BUF)                                                      \
    {                                                                           \
        const int k0_ = (C) * 32;                                               \
        const uint32_t ab_ = base + (uint32_t)((BUF) * PBUF) * 4u;              \
        const uint32_t bb_ = ab_ + 128u * PSTR * 4u;                            \
        _Pragma("unroll")                                                       \
        for (int i = 0; i < 4; i++) {                                           \
            int idx = tid + i * 256;                                            \
            int r = idx >> 3, c4 = idx & 7;                                     \
            cp16(ab_ + 4u * (uint32_t)(r * PSTR + c4 * 4),                      \
                 x + (size_t)(m0 + r) * EMBED + k0_ + c4 * 4);                  \
            cp16(bb_ + 4u * (uint32_t)(r * PSTR + c4 * 4),                      \
                 W + (size_t)(n0 + r) * EMBED + k0_ + c4 * 4);                  \
        }                                                                       \
        CP_COMMIT();                                                            \
    }

    float acc[4][4][4];
    #pragma unroll
    for (int mi = 0; mi < 4; mi++)
        #pragma unroll
        for (int nj = 0; nj < 4; nj++)
            #pragma unroll
            for (int e = 0; e < 4; e++) acc[mi][nj][e] = 0.f;

    PROJ_ISSUE(0, 0);

    for (int c = 0; c < EMBED / 32; c++) {
        const int buf = c & 1;
        CP_WAIT0();
        __syncthreads();
        if (c + 1 < EMBED / 32) PROJ_ISSUE(c + 1, buf ^ 1);

        const uint32_t asb = base + (uint32_t)(buf * PBUF) * 4u;
        const uint32_t bsb = asb + 128u * PSTR * 4u;
        #pragma unroll
        for (int ks = 0; ks < 4; ks++) {
            uint32_t af[4][4], bf4[2][4];
            #pragma unroll
            for (int mi = 0; mi < 4; mi++)
                ldsm_x4(af[mi], asb + 4u * ((uint32_t)(wm + mi * 16) * PSTR + a_l15 * PSTR
                                            + (uint32_t)(ks * 8) + a_hi4));
            #pragma unroll
            for (int p = 0; p < 2; p++)
                ldsm_x4(bf4[p], bsb + 4u * ((uint32_t)(wn + p * 16) * PSTR + b_row * PSTR
                                            + (uint32_t)(ks * 8) + b_c4));
            #pragma unroll
            for (int mi = 0; mi < 4; mi++)
                #pragma unroll
                for (int nj = 0; nj < 4; nj++)
                    mma8(acc[mi][nj], af[mi], &bf4[nj >> 1][(nj & 1) * 2]);
        }
    }

    #pragma unroll
    for (int mi = 0; mi < 4; mi++) {
        int r0 = m0 + wm + mi * 16 + g;
        int r1 = r0 + 8;
        int bb0 = r0 >> 11, s0 = r0 & 2047;
        int bb1 = r1 >> 11, s1 = r1 & 2047;
        #pragma unroll
        for (int nj = 0; nj < 4; nj++) {
            int f = n0 + wn + nj * 8 + 2 * t4;
            int h = f >> 6, dd = f & 63;
            float b0 = bias[f], b1 = bias[f + 1];
            float v0 = to_tf32(acc[mi][nj][0] + b0);
            float v1 = to_tf32(acc[mi][nj][1] + b1);
            float v2 = to_tf32(acc[mi][nj][2] + b0);
            float v3 = to_tf32(acc[mi][nj][3] + b1);
            if (z == 2) {
                // V transposed: [B,H,D,S]
                float* base0 = outp + (((size_t)(bb0 * NHEADS + h)) * HD + dd) * SS;
                float* base1 = outp + (((size_t)(bb1 * NHEADS + h)) * HD + dd) * SS;
                base0[s0] = v0; base0[SS + s0] = v1;
                base1[s1] = v2; base1[SS + s1] = v3;
            } else {
                float* p0 = outp + (((size_t)(bb0 * NHEADS + h)) * SS + s0) * HD + dd;
                float* p1 = outp + (((size_t)(bb1 * NHEADS + h)) * SS + s1) * HD + dd;
                *(float2*)p0 = make_float2(v0, v1);
                *(float2*)p1 = make_float2(v2, v3);
            }
        }
    }
}

// ---------------------------------------------------------------------------
// Kernel 2: attention. 128 threads (4 warps), warp tile 32 rows, k-tile 64.
// NEW: tile processed as four independent 16-key groups, each doing
// MMA1 -> exp/mask -> shfl -> MMA2 back-to-back, so group p+1's tensor work
// overlaps group p's MUFU/SHFL (no barriers between groups).
// Q frags resident; V^T B-frags via ldmatrix; cp.async double buffer.
// ---------------------------------------------------------------------------
#define ASTR 68   // Qs/Ks/Vt stride (272B, %128=16: ldsm conflict-free)

#define OFF_Q  0
#define OFF_K  (128 * ASTR)              // 8704
#define OFF_VT (OFF_K + 2 * 64 * ASTR)   // 17408
#define OFF_MK (OFF_VT + 2 * 64 * ASTR)  // 26112 (ints)
#define ASM_FLOATS (OFF_MK + 128)        // 26240 floats = 104960 B

__global__ void __launch_bounds__(128, 2) attn_kernel(const int* __restrict__ amask,
                                                      float* __restrict__ out)
{
    extern __shared__ float sm[];
    float* Qs = sm;
    const uint32_t qsb = smem_u32(sm);

    const int tid  = threadIdx.x;
    const int wid  = tid >> 5;
    const int lane = tid & 31;
    const int g    = lane >> 2;
    const int t4   = lane & 3;
    const int wm   = wid * 32;

    const uint32_t a_l15 = (uint32_t)(lane & 15);
    const uint32_t a_hi4 = (uint32_t)((lane >> 4) << 2);
    const uint32_t b_row = (uint32_t)(((lane >> 4) << 3) + (lane & 7));
    const uint32_t b_c4  = (uint32_t)(((lane >> 3) & 1) << 2);

    const int bh = blockIdx.x;
    const int b  = bh >> 4;
    const int q0 = blockIdx.y * 128;

    const float* Qb = g_Q + (size_t)bh * SS * HD;
    const float* Kb = g_K + (size_t)bh * SS * HD;
    const float* Vb = g_V + (size_t)bh * HD * SS;   // transposed [d][s]

    // ---- stage Q tile [128x64] (persistent; pre-rounded) ----
    #pragma unroll
    for (int i = 0; i < 16; i++) {
        int idx = tid + i * 128;
        int r = idx >> 4, c4 = idx & 15;
        *(float4*)&Qs[r * ASTR + c4 * 4] = *(const float4*)(Qb + (size_t)(q0 + r) * HD + c4 * 4);
    }

    // issue tile KT's K (64 keys x 64 dims) + V^T (64 dims x 64 keys) + mask
#define ISSUE_TILE(KT, BUF)                                                     \
    {                                                                           \
        const int k0_ = (KT) * 64;                                              \
        const uint32_t kb_ = qsb + 4u * (uint32_t)(OFF_K  + (BUF) * 64 * ASTR); \
        const uint32_t vb_ = qsb + 4u * (uint32_t)(OFF_VT + (BUF) * 64 * ASTR); \
        _Pragma("unroll")                                                       \
        for (int i = 0; i < 8; i++) {                                           \
            int idx = tid + i * 128;                                            \
            int r = idx >> 4, c4 = idx & 15;                                    \
            cp16(kb_ + 4u * (uint32_t)(r * ASTR + c4 * 4),                      \
                 Kb + (size_t)(k0_ + r) * HD + c4 * 4);                         \
            cp16(vb_ + 4u * (uint32_t)(r * ASTR + c4 * 4),                      \
                 Vb + (size_t)r * SS + k0_ + c4 * 4);                           \
        }                                                                       \
        if (tid < 64)                                                           \
            cp4(qsb + 4u * (uint32_t)(OFF_MK + (BUF) * 64 + tid),               \
                amask + (size_t)b * SS + k0_ + tid);                            \
        CP_COMMIT();                                                            \
    }

    ISSUE_TILE(0, 0);

    // ---- resident Q fragments ----
    __syncthreads();
    uint32_t qf[2][8][4];
    #pragma unroll
    for (int mi = 0; mi < 2; mi++)
        #pragma unroll
        for (int ks = 0; ks < 8; ks++)
            ldsm_x4(qf[mi][ks], qsb + 4u * ((uint32_t)(wm + mi * 16 + (int)a_l15) * ASTR
                                            + (uint32_t)(ks * 8) + a_hi4));

    float oacc[2][8][4];
    #pragma unroll
    for (int mi = 0; mi < 2; mi++)
        #pragma unroll
        for (int nj = 0; nj < 8; nj++)
            #pragma unroll
            for (int e = 0; e < 4; e++) oacc[mi][nj][e] = 0.f;
    float lrA[2] = {0.f, 0.f}, lrB[2] = {0.f, 0.f};

    const int srcA = (lane & 28) | (t4 >> 1);
    const int srcB = srcA + 2;
    const bool odd = (t4 & 1) != 0;

    for (int kt = 0; kt < SS / 64; kt++) {
        const int buf = kt & 1;

        CP_WAIT0();        // this thread's copies for tile kt complete
        __syncthreads();   // all copies visible; all warps past compute(kt-1)

        if (kt + 1 < SS / 64) ISSUE_TILE(kt + 1, buf ^ 1);

        const uint32_t ksb = qsb + 4u * (uint32_t)(OFF_K  + buf * 64 * ASTR)
                           + 4u * (b_row * ASTR + b_c4);
        const uint32_t vsb = qsb + 4u * (uint32_t)(OFF_VT + buf * 64 * ASTR)
                           + 4u * (b_row * ASTR + b_c4);
        const int* mki = (const int*)(sm + OFF_MK) + buf * 64;

        // ---- four independent 16-key groups: MMA1 -> exp -> shfl -> MMA2 ----
        #pragma unroll
        for (int p = 0; p < 4; p++) {
            // MMA1 group p: S[32 x 16] for keys [p*16, p*16+16)
            float sg[2][2][4];
            #pragma unroll
            for (int mi = 0; mi < 2; mi++)
                #pragma unroll
                for (int sub = 0; sub < 2; sub++)
                    #pragma unroll
                    for (int e = 0; e < 4; e++) sg[mi][sub][e] = 0.f;

            #pragma unroll
            for (int ks = 0; ks < 8; ks++) {
                uint32_t bq[4];
                ldsm_x4(bq, ksb + 4u * (uint32_t)(p * 16 * ASTR + ks * 8));
                #pragma unroll
                for (int mi = 0; mi < 2; mi++) {
                    mma8(sg[mi][0], qf[mi][ks], &bq[0]);
                    mma8(sg[mi][1], qf[mi][ks], &bq[2]);
                }
            }

            // softmax piece for this group's 16 keys (nj = 2p, 2p+1)
            #pragma unroll
            for (int sub = 0; sub < 2; sub++) {
                const int nj = 2 * p + sub;
                bool m0 = mki[nj * 8 + 2 * t4] != 0;
                bool m1 = mki[nj * 8 + 2 * t4 + 1] != 0;
                #pragma unroll
                for (int mi = 0; mi < 2; mi++) {
                    float p0 = m0 ? __expf(sg[mi][sub][0] * SCALE) : 0.f;
                    float p1 = m1 ? __expf(sg[mi][sub][1] * SCALE) : 0.f;
                    float p2 = m0 ? __expf(sg[mi][sub][2] * SCALE) : 0.f;
                    float p3 = m1 ? __expf(sg[mi][sub][3] * SCALE) : 0.f;
                    sg[mi][sub][0] = p0; sg[mi][sub][1] = p1;
                    sg[mi][sub][2] = p2; sg[mi][sub][3] = p3;
                    lrA[mi] += p0 + p1;
                    lrB[mi] += p2 + p3;
                }
            }

            // MMA2 for this group's two 8-key chunks (ks2 = 2p, 2p+1)
            #pragma unroll
            for (int sub = 0; sub < 2; sub++) {
                const int ks2 = 2 * p + sub;
                uint32_t pa[2][4];
                #pragma unroll
                for (int mi = 0; mi < 2; mi++) {
                    float v0 = __shfl_sync(0xFFFFFFFFu, sg[mi][sub][0], srcA);
                    float v1 = __shfl_sync(0xFFFFFFFFu, sg[mi][sub][1], srcA);
                    float v2 = __shfl_sync(0xFFFFFFFFu, sg[mi][sub][2], srcA);
                    float v3 = __shfl_sync(0xFFFFFFFFu, sg[mi][sub][3], srcA);
                    float w0 = __shfl_sync(0xFFFFFFFFu, sg[mi][sub][0], srcB);
                    float w1 = __shfl_sync(0xFFFFFFFFu, sg[mi][sub][1], srcB);
                    float w2 = __shfl_sync(0xFFFFFFFFu, sg[mi][sub][2], srcB);
                    float w3 = __shfl_sync(0xFFFFFFFFu, sg[mi][sub][3], srcB);
                    pa[mi][0] = __float_as_uint(to_tf32(odd ? v1 : v0));
                    pa[mi][1] = __float_as_uint(to_tf32(odd ? v3 : v2));
                    pa[mi][2] = __float_as_uint(to_tf32(odd ? w1 : w0));
                    pa[mi][3] = __float_as_uint(to_tf32(odd ? w3 : w2));
                }
                uint32_t bv[4][4];
                #pragma unroll
                for (int pp = 0; pp < 4; pp++)   // 64 dims = 4 x (16-row ldsm pair)
                    ldsm_x4(bv[pp], vsb + 4u * (uint32_t)(pp * 16 * ASTR + ks2 * 8));
                #pragma unroll
                for (int mi = 0; mi < 2; mi++)
                    #pragma unroll
                    for (int nj8 = 0; nj8 < 8; nj8++)
                        mma8(oacc[mi][nj8], pa[mi], &bv[nj8 >> 1][(nj8 & 1) * 2]);
            }
        }
    }

    // ---- reduce row sums across quad, normalize, store ----
    #pragma unroll
    for (int mi = 0; mi < 2; mi++) {
        lrA[mi] += __shfl_xor_sync(0xFFFFFFFFu, lrA[mi], 1);
        lrA[mi] += __shfl_xor_sync(0xFFFFFFFFu, lrA[mi], 2);
        lrB[mi] += __shfl_xor_sync(0xFFFFFFFFu, lrB[mi], 1);
        lrB[mi] += __shfl_xor_sync(0xFFFFFFFFu, lrB[mi], 2);
    }

    #pragma unroll
    for (int mi = 0; mi < 2; mi++) {
        int r0 = wm + mi * 16 + g;
        int r1 = r0 + 8;
        float il0 = 1.f / lrA[mi];
        float il1 = 1.f / lrB[mi];
        #pragma unroll
        for (int nj = 0; nj < 8; nj++) {
            int c0 = nj * 8 + 2 * t4;
            float* p0 = out + ((size_t)bh * SS + q0 + r0) * HD + c0;
            float* p1 = out + ((size_t)bh * SS + q0 + r1) * HD + c0;
            *(float2*)p0 = make_float2(oacc[mi][nj][0] * il0, oacc[mi][nj][1] * il0);
            *(float2*)p1 = make_float2(oacc[mi][nj][2] * il1, oacc[mi][nj][3] * il1);
        }
    }
}

// ---------------------------------------------------------------------------
extern "C" void kernel_launch(void* const* d_in, const int* in_sizes, int n_in,
                              void* d_out, int out_size)
{
    (void)in_sizes; (void)n_in; (void)out_size;
    const float* q  = (const float*)d_in[0];
    const float* k  = (const float*)d_in[1];
    const float* v  = (const float*)d_in[2];
    const int*   am = (const int*)  d_in[3];
    const float* Wq = (const float*)d_in[4];
    const float* bq = (const float*)d_in[5];
    const float* Wk = (const float*)d_in[6];
    const float* bk = (const float*)d_in[7];
    const float* Wv = (const float*)d_in[8];
    const float* bv = (const float*)d_in[9];

    static int attr_set = 0;
    if (!attr_set) {
        cudaFuncSetAttribute(attn_kernel, cudaFuncAttributeMaxDynamicSharedMemorySize,
                             ASM_FLOATS * (int)sizeof(float));
        cudaFuncSetAttribute(proj_kernel, cudaFuncAttributeMaxDynamicSharedMemorySize,
                             PROJ_SMEM_BYTES);
        attr_set = 1;
    }

    const int nx4 = MROWS * EMBED / 4;
    dim3 rgrid((nx4 + 255) / 256, 6);
    round_all_kernel<<<rgrid, 256>>>(q, k, v, Wq, Wk, Wv);

    dim3 pgrid(EMBED / 128, MROWS / 128, 3);
    proj_kernel<<<pgrid, 256, PROJ_SMEM_BYTES>>>(bq, bk, bv);

    dim3 agrid(BHD, SS / 128);
    attn_kernel<<<agrid, 128, ASM_FLOATS * sizeof(float)>>>(am, (float*)d_out);
}

// round 13
// speedup vs baseline: 2.4950x; 1.6530x over previous
#include <cuda_runtime.h>
#include <cuda_fp16.h>
#include <cstdint>
#include <math.h>

#define EMBED 1024
#define NHEADS 16
#define HD 64
#define BB 2
#define SS 2048
#define BHD (BB*NHEADS)   // 32
#define MROWS (BB*SS)     // 4096
#define SCALE 0.03125f    // 1/sqrt(1024)

// fp16 copies of inputs
__device__ __half g_Xh[3][(size_t)MROWS*EMBED];
__device__ __half g_Wh[3][(size_t)EMBED*EMBED];
// Projected Q,K in [B,H,S,D]; V TRANSPOSED as [B,H,D,S]. All fp16.
__device__ __half g_Q[(size_t)BB*NHEADS*SS*HD];
__device__ __half g_K[(size_t)BB*NHEADS*SS*HD];
__device__ __half g_V[(size_t)BB*NHEADS*SS*HD];

__device__ __forceinline__ uint32_t smem_u32(const void* p) {
    uint32_t a;
    asm("{ .reg .u64 t; cvta.to.shared.u64 t, %1; cvt.u32.u64 %0, t; }" : "=r"(a) : "l"(p));
    return a;
}

__device__ __forceinline__ uint32_t packh2(float lo, float hi) {
    __half2 h = __floats2half2_rn(lo, hi);
    return *(uint32_t*)&h;
}

// D = A(16x16 f16) * B(16x8 f16) + D, f32 accum. row.col.
__device__ __forceinline__ void mma16(float* d, const uint32_t* a, uint32_t b0, uint32_t b1) {
    asm volatile(
        "mma.sync.aligned.m16n8k16.row.col.f32.f16.f16.f32 "
        "{%0,%1,%2,%3}, {%4,%5,%6,%7}, {%8,%9}, {%0,%1,%2,%3};"
        : "+f"(d[0]), "+f"(d[1]), "+f"(d[2]), "+f"(d[3])
        : "r"(a[0]), "r"(a[1]), "r"(a[2]), "r"(a[3]), "r"(b0), "r"(b1));
}

// ldmatrix x4 of real b16 (fp16) data
__device__ __forceinline__ void ldsm_x4(uint32_t* r, uint32_t addr) {
    asm volatile("ldmatrix.sync.aligned.m8n8.x4.shared.b16 {%0,%1,%2,%3}, [%4];"
        : "=r"(r[0]), "=r"(r[1]), "=r"(r[2]), "=r"(r[3]) : "r"(addr));
}

// cp.async helpers
__device__ __forceinline__ void cp16(uint32_t dst, const void* src) {
    asm volatile("cp.async.cg.shared.global [%0], [%1], 16;" :: "r"(dst), "l"(src));
}
__device__ __forceinline__ void cp4(uint32_t dst, const void* src) {
    asm volatile("cp.async.ca.shared.global [%0], [%1], 4;" :: "r"(dst), "l"(src));
}
#define CP_COMMIT() asm volatile("cp.async.commit_group;" ::: "memory")
#define CP_WAIT0()  asm volatile("cp.async.wait_group 0;" ::: "memory")

// ---------------------------------------------------------------------------
// Kernel 0: fused f32 -> fp16 conversion of all 6 input arrays
// ---------------------------------------------------------------------------
__global__ void __launch_bounds__(256) cvt_all_kernel(
    const float* __restrict__ s0, const float* __restrict__ s1, const float* __restrict__ s2,
    const float* __restrict__ s3, const float* __restrict__ s4, const float* __restrict__ s5)
{
    const int z = blockIdx.y;
    const int nx8 = MROWS * EMBED / 8;
    const int nw8 = EMBED * EMBED / 8;
    const int n8 = (z < 3) ? nx8 : nw8;
    int i = blockIdx.x * 256 + threadIdx.x;
    if (i >= n8) return;
    const float* src = (z == 0) ? s0 : (z == 1) ? s1 : (z == 2) ? s2
                     : (z == 3) ? s3 : (z == 4) ? s4 : s5;
    __half* dst = (z < 3) ? g_Xh[z] : g_Wh[z - 3];
    const float4* sp = ((const float4*)src) + (size_t)i * 2;
    float4 v0 = sp[0], v1 = sp[1];
    uint4 o;
    o.x = packh2(v0.x, v0.y);
    o.y = packh2(v0.z, v0.w);
    o.z = packh2(v1.x, v1.y);
    o.w = packh2(v1.z, v1.w);
    ((uint4*)dst)[i] = o;
}

// ---------------------------------------------------------------------------
// Kernel 1: QKV projection  y = fp16(x @ W^T + b)
// Q,K -> [B,H,S,D];  V -> [B,H,D,S] (transposed).
// BM=BN=128, BK=64 (fp16). 8 warps as 2x4, warp tile 64x32, m16n8k16.
// cp.async double-buffered staging, 1 barrier/chunk (16 chunks).
// ---------------------------------------------------------------------------
#define PROWB 144          // smem row bytes: 64 fp16 + 8 pad (%128=16 -> ldsm ok)
#define PBUFB (128*PROWB)  // one operand tile = 18432 B
#define PROJ_SMEM_BYTES (4 * PBUFB)   // A+B x 2 buffers = 73728

__global__ void __launch_bounds__(256, 2) proj_kernel(
    const float* __restrict__ bq, const float* __restrict__ bk, const float* __restrict__ bv)
{
    extern __shared__ char psm[];
    const uint32_t base = smem_u32(psm);

    const int z = blockIdx.z;
    const __half* x = g_Xh[z];
    const __half* W = g_Wh[z];
    const float* bias = (z == 0) ? bq : (z == 1) ? bk : bv;
    __half* outp = (z == 0) ? g_Q : (z == 1) ? g_K : g_V;

    const int m0 = blockIdx.y * 128;
    const int n0 = blockIdx.x * 128;
    const int tid  = threadIdx.x;
    const int lane = tid & 31;
    const int wid  = tid >> 5;
    const int g    = lane >> 2;
    const int t4   = lane & 3;
    const int wm   = (wid >> 2) * 64;
    const int wn   = (wid & 3) * 32;

    // ldmatrix lane addressing (A and B identical): row=(lane&15), +16B if lane>=16
    const uint32_t fr = (uint32_t)(lane & 15) * PROWB + (uint32_t)((lane >> 4) << 4);

#define PROJ_ISSUE(C, BUF)                                                      \
    {                                                                           \
        const int k0_ = (C) * 64;                                               \
        const uint32_t ab_ = base + (uint32_t)((BUF) * 2 * PBUFB);              \
        const uint32_t bb_ = ab_ + PBUFB;                                       \
        _Pragma("unroll")                                                       \
        for (int i = 0; i < 4; i++) {                                           \
            int idx = tid + i * 256;                                            \
            int r = idx >> 3, c8 = idx & 7;                                     \
            cp16(ab_ + (uint32_t)(r * PROWB + c8 * 16),                         \
                 x + (size_t)(m0 + r) * EMBED + k0_ + c8 * 8);                  \
            cp16(bb_ + (uint32_t)(r * PROWB + c8 * 16),                         \
                 W + (size_t)(n0 + r) * EMBED + k0_ + c8 * 8);                  \
        }                                                                       \
        CP_COMMIT();                                                            \
    }

    float acc[4][4][4];
    #pragma unroll
    for (int mi = 0; mi < 4; mi++)
        #pragma unroll
        for (int nj = 0; nj < 4; nj++)
            #pragma unroll
            for (int e = 0; e < 4; e++) acc[mi][nj][e] = 0.f;

    PROJ_ISSUE(0, 0);

    for (int c = 0; c < EMBED / 64; c++) {
        const int buf = c & 1;
        CP_WAIT0();
        __syncthreads();
        if (c + 1 < EMBED / 64) PROJ_ISSUE(c + 1, buf ^ 1);

        const uint32_t asb = base + (uint32_t)(buf * 2 * PBUFB) + fr;
        const uint32_t bsb = asb + PBUFB;
        #pragma unroll
        for (int ks = 0; ks < 4; ks++) {   // k-steps of 16 within BK=64
            uint32_t af[4][4], bf[2][4];
            #pragma unroll
            for (int mi = 0; mi < 4; mi++)
                ldsm_x4(af[mi], asb + (uint32_t)((wm + mi * 16) * PROWB + ks * 32));
            #pragma unroll
            for (int pb = 0; pb < 2; pb++)
                ldsm_x4(bf[pb], bsb + (uint32_t)((wn + pb * 16) * PROWB + ks * 32));
            #pragma unroll
            for (int mi = 0; mi < 4; mi++)
                #pragma unroll
                for (int pb = 0; pb < 2; pb++) {
                    mma16(acc[mi][2 * pb],     af[mi], bf[pb][0], bf[pb][2]);
                    mma16(acc[mi][2 * pb + 1], af[mi], bf[pb][1], bf[pb][3]);
                }
        }
    }

    // epilogue: +bias, fp16-round, scatter
    #pragma unroll
    for (int mi = 0; mi < 4; mi++) {
        int r0 = m0 + wm + mi * 16 + g;
        int r1 = r0 + 8;
        int bb0 = r0 >> 11, s0 = r0 & 2047;
        int bb1 = r1 >> 11, s1 = r1 & 2047;
        #pragma unroll
        for (int nj = 0; nj < 4; nj++) {
            int f = n0 + wn + nj * 8 + 2 * t4;
            int h = f >> 6, dd = f & 63;
            float b0 = bias[f], b1 = bias[f + 1];
            float v0 = acc[mi][nj][0] + b0;
            float v1 = acc[mi][nj][1] + b1;
            float v2 = acc[mi][nj][2] + b0;
            float v3 = acc[mi][nj][3] + b1;
            if (z == 2) {
                // V transposed: [B,H,D,S]
                __half* p0 = outp + ((size_t)(bb0 * NHEADS + h) * HD + dd) * SS + s0;
                __half* p1 = outp + ((size_t)(bb1 * NHEADS + h) * HD + dd) * SS + s1;
                p0[0] = __float2half_rn(v0); p0[SS] = __float2half_rn(v1);
                p1[0] = __float2half_rn(v2); p1[SS] = __float2half_rn(v3);
            } else {
                *(uint32_t*)(outp + ((size_t)(bb0 * NHEADS + h) * SS + s0) * HD + dd) = packh2(v0, v1);
                *(uint32_t*)(outp + ((size_t)(bb1 * NHEADS + h) * SS + s1) * HD + dd) = packh2(v2, v3);
            }
        }
    }
}

// ---------------------------------------------------------------------------
// Kernel 2: attention, fp16 m16n8k16. 128 threads (4 warps), warp tile 32
// rows, k-tile 64 keys in four 16-key groups. S-accumulator layout == A-frag
// layout => P pack needs NO shuffles. Q frags resident; V^T/K B-frags via
// ldmatrix; cp.async double buffer; 1 barrier/tile; row sums in regs.
// ---------------------------------------------------------------------------
#define AROWB 144                        // 64 fp16 + pad (%128=16)
#define OFFB_Q  0                        // 128*144 = 18432
#define OFFB_K  18432                    // 2 x 64*144 = 18432
#define OFFB_VT 36864                    // 2 x 64*144 = 18432
#define OFFB_MK 55296                    // 128 ints = 512
#define ATTN_SMEM_BYTES 55808

__global__ void __launch_bounds__(128, 2) attn_kernel(const int* __restrict__ amask,
                                                      float* __restrict__ out)
{
    extern __shared__ char smx[];
    const uint32_t sb = smem_u32(smx);

    const int tid  = threadIdx.x;
    const int wid  = tid >> 5;
    const int lane = tid & 31;
    const int g    = lane >> 2;
    const int t4   = lane & 3;
    const int wm   = wid * 32;

    const uint32_t fr = (uint32_t)(lane & 15) * AROWB + (uint32_t)((lane >> 4) << 4);

    const int bh = blockIdx.x;
    const int b  = bh >> 4;
    const int q0 = blockIdx.y * 128;

    const __half* Qb = g_Q + (size_t)bh * SS * HD;
    const __half* Kb = g_K + (size_t)bh * SS * HD;
    const __half* Vb = g_V + (size_t)bh * HD * SS;   // transposed [d][s]

    // ---- stage Q tile [128x64] fp16 (persistent) ----
    #pragma unroll
    for (int i = 0; i < 8; i++) {
        int idx = tid + i * 128;
        int r = idx >> 3, c8 = idx & 7;
        *(uint4*)(smx + r * AROWB + c8 * 16) =
            *(const uint4*)(Qb + (size_t)(q0 + r) * HD + c8 * 8);
    }

    // issue tile KT's K (64 keys x 64 d) + V^T (64 d x 64 keys) + mask
#define ISSUE_TILE(KT, BUF)                                                     \
    {                                                                           \
        const int k0_ = (KT) * 64;                                              \
        const uint32_t kb_ = sb + (uint32_t)(OFFB_K  + (BUF) * 64 * AROWB);     \
        const uint32_t vb_ = sb + (uint32_t)(OFFB_VT + (BUF) * 64 * AROWB);     \
        _Pragma("unroll")                                                       \
        for (int i = 0; i < 4; i++) {                                           \
            int idx = tid + i * 128;                                            \
            int r = idx >> 3, c8 = idx & 7;                                     \
            cp16(kb_ + (uint32_t)(r * AROWB + c8 * 16),                         \
                 Kb + (size_t)(k0_ + r) * HD + c8 * 8);                         \
            cp16(vb_ + (uint32_t)(r * AROWB + c8 * 16),                         \
                 Vb + (size_t)r * SS + k0_ + c8 * 8);                           \
        }                                                                       \
        if (tid < 64)                                                           \
            cp4(sb + (uint32_t)(OFFB_MK + ((BUF) * 64 + tid) * 4),              \
                amask + (size_t)b * SS + k0_ + tid);                            \
        CP_COMMIT();                                                            \
    }

    ISSUE_TILE(0, 0);

    // ---- resident Q fragments: 2 mi x 4 ksteps x 4 regs ----
    __syncthreads();
    uint32_t qf[2][4][4];
    #pragma unroll
    for (int mi = 0; mi < 2; mi++)
        #pragma unroll
        for (int ks = 0; ks < 4; ks++)
            ldsm_x4(qf[mi][ks], sb + fr + (uint32_t)((wm + mi * 16) * AROWB + ks * 32));

    float oacc[2][8][4];
    #pragma unroll
    for (int mi = 0; mi < 2; mi++)
        #pragma unroll
        for (int nj = 0; nj < 8; nj++)
            #pragma unroll
            for (int e = 0; e < 4; e++) oacc[mi][nj][e] = 0.f;
    float lrA[2] = {0.f, 0.f}, lrB[2] = {0.f, 0.f};

    for (int kt = 0; kt < SS / 64; kt++) {
        const int buf = kt & 1;

        CP_WAIT0();
        __syncthreads();
        if (kt + 1 < SS / 64) ISSUE_TILE(kt + 1, buf ^ 1);

        const uint32_t ksb = sb + (uint32_t)(OFFB_K  + buf * 64 * AROWB) + fr;
        const uint32_t vsb = sb + (uint32_t)(OFFB_VT + buf * 64 * AROWB) + fr;
        const int* mki = (const int*)(smx + OFFB_MK) + buf * 64;

        // ---- four independent 16-key groups ----
        #pragma unroll
        for (int p = 0; p < 4; p++) {
            // MMA1: S[32 x 16] for keys [p*16, p*16+16)
            float sg[2][2][4];
            #pragma unroll
            for (int mi = 0; mi < 2; mi++)
                #pragma unroll
                for (int sub = 0; sub < 2; sub++)
                    #pragma unroll
                    for (int e = 0; e < 4; e++) sg[mi][sub][e] = 0.f;

            #pragma unroll
            for (int ks = 0; ks < 4; ks++) {   // d-ksteps of 16
                uint32_t bq[4];
                ldsm_x4(bq, ksb + (uint32_t)(p * 16 * AROWB + ks * 32));
                #pragma unroll
                for (int mi = 0; mi < 2; mi++) {
                    mma16(sg[mi][0], qf[mi][ks], bq[0], bq[2]);
                    mma16(sg[mi][1], qf[mi][ks], bq[1], bq[3]);
                }
            }

            // softmax piece (nj = 2p, 2p+1)
            #pragma unroll
            for (int sub = 0; sub < 2; sub++) {
                const int nj = 2 * p + sub;
                bool m0 = mki[nj * 8 + 2 * t4] != 0;
                bool m1 = mki[nj * 8 + 2 * t4 + 1] != 0;
                #pragma unroll
                for (int mi = 0; mi < 2; mi++) {
                    float p0 = m0 ? __expf(sg[mi][sub][0] * SCALE) : 0.f;
                    float p1 = m1 ? __expf(sg[mi][sub][1] * SCALE) : 0.f;
                    float p2 = m0 ? __expf(sg[mi][sub][2] * SCALE) : 0.f;
                    float p3 = m1 ? __expf(sg[mi][sub][3] * SCALE) : 0.f;
                    sg[mi][sub][0] = p0; sg[mi][sub][1] = p1;
                    sg[mi][sub][2] = p2; sg[mi][sub][3] = p3;
                    lrA[mi] += p0 + p1;
                    lrB[mi] += p2 + p3;
                }
            }

            // MMA2: O += P[32 x 16] V[16 x 64]
            // A-frag = own accumulators packed (acc layout == A-frag layout)
            uint32_t pa[2][4];
            #pragma unroll
            for (int mi = 0; mi < 2; mi++) {
                pa[mi][0] = packh2(sg[mi][0][0], sg[mi][0][1]);
                pa[mi][1] = packh2(sg[mi][0][2], sg[mi][0][3]);
                pa[mi][2] = packh2(sg[mi][1][0], sg[mi][1][1]);
                pa[mi][3] = packh2(sg[mi][1][2], sg[mi][1][3]);
            }
            #pragma unroll
            for (int pp = 0; pp < 4; pp++) {   // 64 dims = 4 x 16-d groups
                uint32_t bv[4];
                ldsm_x4(bv, vsb + (uint32_t)(pp * 16 * AROWB + p * 32));
                #pragma unroll
                for (int mi = 0; mi < 2; mi++) {
                    mma16(oacc[mi][2 * pp],     pa[mi], bv[0], bv[2]);
                    mma16(oacc[mi][2 * pp + 1], pa[mi], bv[1], bv[3]);
                }
            }
        }
    }

    // ---- reduce row sums across quad, normalize, store ----
    #pragma unroll
    for (int mi = 0; mi < 2; mi++) {
        lrA[mi] += __shfl_xor_sync(0xFFFFFFFFu, lrA[mi], 1);
        lrA[mi] += __shfl_xor_sync(0xFFFFFFFFu, lrA[mi], 2);
        lrB[mi] += __shfl_xor_sync(0xFFFFFFFFu, lrB[mi], 1);
        lrB[mi] += __shfl_xor_sync(0xFFFFFFFFu, lrB[mi], 2);
    }

    #pragma unroll
    for (int mi = 0; mi < 2; mi++) {
        int r0 = wm + mi * 16 + g;
        int r1 = r0 + 8;
        float il0 = 1.f / lrA[mi];
        float il1 = 1.f / lrB[mi];
        #pragma unroll
        for (int nj = 0; nj < 8; nj++) {
            int c0 = nj * 8 + 2 * t4;
            float* p0 = out + ((size_t)bh * SS + q0 + r0) * HD + c0;
            float* p1 = out + ((size_t)bh * SS + q0 + r1) * HD + c0;
            *(float2*)p0 = make_float2(oacc[mi][nj][0] * il0, oacc[mi][nj][1] * il0);
            *(float2*)p1 = make_float2(oacc[mi][nj][2] * il1, oacc[mi][nj][3] * il1);
        }
    }
}

// ---------------------------------------------------------------------------
extern "C" void kernel_launch(void* const* d_in, const int* in_sizes, int n_in,
                              void* d_out, int out_size)
{
    (void)in_sizes; (void)n_in; (void)out_size;
    const float* q  = (const float*)d_in[0];
    const float* k  = (const float*)d_in[1];
    const float* v  = (const float*)d_in[2];
    const int*   am = (const int*)  d_in[3];
    const float* Wq = (const float*)d_in[4];
    const float* bq = (const float*)d_in[5];
    const float* Wk = (const float*)d_in[6];
    const float* bk = (const float*)d_in[7];
    const float* Wv = (const float*)d_in[8];
    const float* bv = (const float*)d_in[9];

    static int attr_set = 0;
    if (!attr_set) {
        cudaFuncSetAttribute(attn_kernel, cudaFuncAttributeMaxDynamicSharedMemorySize,
                             ATTN_SMEM_BYTES);
        cudaFuncSetAttribute(proj_kernel, cudaFuncAttributeMaxDynamicSharedMemorySize,
                             PROJ_SMEM_BYTES);
        attr_set = 1;
    }

    const int nx8 = MROWS * EMBED / 8;   // 524288
    dim3 cgrid((nx8 + 255) / 256, 6);
    cvt_all_kernel<<<cgrid, 256>>>(q, k, v, Wq, Wk, Wv);

    dim3 pgrid(EMBED / 128, MROWS / 128, 3);   // (8, 32, 3)
    proj_kernel<<<pgrid, 256, PROJ_SMEM_BYTES>>>(bq, bk, bv);

    dim3 agrid(BHD, SS / 128);                 // (32, 16)
    attn_kernel<<<agrid, 128, ATTN_SMEM_BYTES>>>(am, (float*)d_out);
}

// round 16
// speedup vs baseline: 2.6654x; 1.0683x over previous
#include <cuda_runtime.h>
#include <cuda_fp16.h>
#include <cstdint>
#include <math.h>

#define EMBED 1024
#define NHEADS 16
#define HD 64
#define BB 2
#define SS 2048
#define BHD (BB*NHEADS)   // 32
#define MROWS (BB*SS)     // 4096
#define SCALE 0.03125f    // 1/sqrt(1024)
#define SCL2E 0.0450844f  // SCALE * log2(e)

// fp16 copies of inputs
__device__ __half g_Xh[3][(size_t)MROWS*EMBED];
__device__ __half g_Wh[3][(size_t)EMBED*EMBED];
// Projected Q,K in [B,H,S,D]; V TRANSPOSED as [B,H,D,S]. All fp16.
__device__ __half g_Q[(size_t)BB*NHEADS*SS*HD];
__device__ __half g_K[(size_t)BB*NHEADS*SS*HD];
__device__ __half g_V[(size_t)BB*NHEADS*SS*HD];

__device__ __forceinline__ uint32_t smem_u32(const void* p) {
    uint32_t a;
    asm("{ .reg .u64 t; cvta.to.shared.u64 t, %1; cvt.u32.u64 %0, t; }" : "=r"(a) : "l"(p));
    return a;
}

__device__ __forceinline__ uint32_t packh2(float lo, float hi) {
    __half2 h = __floats2half2_rn(lo, hi);
    return *(uint32_t*)&h;
}

// D = A(16x16 f16) * B(16x8 f16) + D, f32 accum. row.col.
__device__ __forceinline__ void mma16(float* d, const uint32_t* a, uint32_t b0, uint32_t b1) {
    asm volatile(
        "mma.sync.aligned.m16n8k16.row.col.f32.f16.f16.f32 "
        "{%0,%1,%2,%3}, {%4,%5,%6,%7}, {%8,%9}, {%0,%1,%2,%3};"
        : "+f"(d[0]), "+f"(d[1]), "+f"(d[2]), "+f"(d[3])
        : "r"(a[0]), "r"(a[1]), "r"(a[2]), "r"(a[3]), "r"(b0), "r"(b1));
}

// ldmatrix x4 of real b16 (fp16) data
__device__ __forceinline__ void ldsm_x4(uint32_t* r, uint32_t addr) {
    asm volatile("ldmatrix.sync.aligned.m8n8.x4.shared.b16 {%0,%1,%2,%3}, [%4];"
        : "=r"(r[0]), "=r"(r[1]), "=r"(r[2]), "=r"(r[3]) : "r"(addr));
}

// cp.async helpers
__device__ __forceinline__ void cp16(uint32_t dst, const void* src) {
    asm volatile("cp.async.cg.shared.global [%0], [%1], 16;" :: "r"(dst), "l"(src));
}
__device__ __forceinline__ void cp4(uint32_t dst, const void* src) {
    asm volatile("cp.async.ca.shared.global [%0], [%1], 4;" :: "r"(dst), "l"(src));
}
#define CP_COMMIT() asm volatile("cp.async.commit_group;" ::: "memory")
#define CP_WAIT0()  asm volatile("cp.async.wait_group 0;" ::: "memory")

// ---------------------------------------------------------------------------
// Kernel 0: fused f32 -> fp16 conversion of all 6 input arrays
// ---------------------------------------------------------------------------
__global__ void __launch_bounds__(256) cvt_all_kernel(
    const float* __restrict__ s0, const float* __restrict__ s1, const float* __restrict__ s2,
    const float* __restrict__ s3, const float* __restrict__ s4, const float* __restrict__ s5)
{
    const int z = blockIdx.y;
    const int nx8 = MROWS * EMBED / 8;
    const int nw8 = EMBED * EMBED / 8;
    const int n8 = (z < 3) ? nx8 : nw8;
    int i = blockIdx.x * 256 + threadIdx.x;
    if (i >= n8) return;
    const float* src = (z == 0) ? s0 : (z == 1) ? s1 : (z == 2) ? s2
                     : (z == 3) ? s3 : (z == 4) ? s4 : s5;
    __half* dst = (z < 3) ? g_Xh[z] : g_Wh[z - 3];
    const float4* sp = ((const float4*)src) + (size_t)i * 2;
    float4 v0 = sp[0], v1 = sp[1];
    uint4 o;
    o.x = packh2(v0.x, v0.y);
    o.y = packh2(v0.z, v0.w);
    o.z = packh2(v1.x, v1.y);
    o.w = packh2(v1.z, v1.w);
    ((uint4*)dst)[i] = o;
}

// ---------------------------------------------------------------------------
// Kernel 1: QKV projection  y = fp16(x @ W^T + b)
// Q,K -> [B,H,S,D];  V -> [B,H,D,S] (transposed).
// BM=BN=128, BK=64 (fp16). 8 warps as 2x4, warp tile 64x32, m16n8k16.
// cp.async double-buffered staging, 1 barrier/chunk (16 chunks).
// ---------------------------------------------------------------------------
#define PROWB 144          // smem row bytes: 64 fp16 + 8 pad (%128=16 -> ldsm ok)
#define PBUFB (128*PROWB)  // one operand tile = 18432 B
#define PROJ_SMEM_BYTES (4 * PBUFB)   // A+B x 2 buffers = 73728

__global__ void __launch_bounds__(256, 2) proj_kernel(
    const float* __restrict__ bq, const float* __restrict__ bk, const float* __restrict__ bv)
{
    extern __shared__ char psm[];
    const uint32_t base = smem_u32(psm);

    const int z = blockIdx.z;
    const __half* x = g_Xh[z];
    const __half* W = g_Wh[z];
    const float* bias = (z == 0) ? bq : (z == 1) ? bk : bv;
    __half* outp = (z == 0) ? g_Q : (z == 1) ? g_K : g_V;

    const int m0 = blockIdx.y * 128;
    const int n0 = blockIdx.x * 128;
    const int tid  = threadIdx.x;
    const int lane = tid & 31;
    const int wid  = tid >> 5;
    const int g    = lane >> 2;
    const int t4   = lane & 3;
    const int wm   = (wid >> 2) * 64;
    const int wn   = (wid & 3) * 32;

    const uint32_t fr = (uint32_t)(lane & 15) * PROWB + (uint32_t)((lane >> 4) << 4);

#define PROJ_ISSUE(C, BUF)                                                      \
    {                                                                           \
        const int k0_ = (C) * 64;                                               \
        const uint32_t ab_ = base + (uint32_t)((BUF) * 2 * PBUFB);              \
        const uint32_t bb_ = ab_ + PBUFB;                                       \
        _Pragma("unroll")                                                       \
        for (int i = 0; i < 4; i++) {                                           \
            int idx = tid + i * 256;                                            \
            int r = idx >> 3, c8 = idx & 7;                                     \
            cp16(ab_ + (uint32_t)(r * PROWB + c8 * 16),                         \
                 x + (size_t)(m0 + r) * EMBED + k0_ + c8 * 8);                  \
            cp16(bb_ + (uint32_t)(r * PROWB + c8 * 16),                         \
                 W + (size_t)(n0 + r) * EMBED + k0_ + c8 * 8);                  \
        }                                                                       \
        CP_COMMIT();                                                            \
    }

    float acc[4][4][4];
    #pragma unroll
    for (int mi = 0; mi < 4; mi++)
        #pragma unroll
        for (int nj = 0; nj < 4; nj++)
            #pragma unroll
            for (int e = 0; e < 4; e++) acc[mi][nj][e] = 0.f;

    PROJ_ISSUE(0, 0);

    for (int c = 0; c < EMBED / 64; c++) {
        const int buf = c & 1;
        CP_WAIT0();
        __syncthreads();
        if (c + 1 < EMBED / 64) PROJ_ISSUE(c + 1, buf ^ 1);

        const uint32_t asb = base + (uint32_t)(buf * 2 * PBUFB) + fr;
        const uint32_t bsb = asb + PBUFB;
        #pragma unroll
        for (int ks = 0; ks < 4; ks++) {
            uint32_t af[4][4], bf[2][4];
            #pragma unroll
            for (int mi = 0; mi < 4; mi++)
                ldsm_x4(af[mi], asb + (uint32_t)((wm + mi * 16) * PROWB + ks * 32));
            #pragma unroll
            for (int pb = 0; pb < 2; pb++)
                ldsm_x4(bf[pb], bsb + (uint32_t)((wn + pb * 16) * PROWB + ks * 32));
            #pragma unroll
            for (int mi = 0; mi < 4; mi++)
                #pragma unroll
                for (int pb = 0; pb < 2; pb++) {
                    mma16(acc[mi][2 * pb],     af[mi], bf[pb][0], bf[pb][2]);
                    mma16(acc[mi][2 * pb + 1], af[mi], bf[pb][1], bf[pb][3]);
                }
        }
    }

    // epilogue: +bias, fp16-round, scatter
    #pragma unroll
    for (int mi = 0; mi < 4; mi++) {
        int r0 = m0 + wm + mi * 16 + g;
        int r1 = r0 + 8;
        int bb0 = r0 >> 11, s0 = r0 & 2047;
        int bb1 = r1 >> 11, s1 = r1 & 2047;
        #pragma unroll
        for (int nj = 0; nj < 4; nj++) {
            int f = n0 + wn + nj * 8 + 2 * t4;
            int h = f >> 6, dd = f & 63;
            float b0 = bias[f], b1 = bias[f + 1];
            float v0 = acc[mi][nj][0] + b0;
            float v1 = acc[mi][nj][1] + b1;
            float v2 = acc[mi][nj][2] + b0;
            float v3 = acc[mi][nj][3] + b1;
            if (z == 2) {
                // V transposed: [B,H,D,S]
                __half* p0 = outp + ((size_t)(bb0 * NHEADS + h) * HD + dd) * SS + s0;
                __half* p1 = outp + ((size_t)(bb1 * NHEADS + h) * HD + dd) * SS + s1;
                p0[0] = __float2half_rn(v0); p0[SS] = __float2half_rn(v1);
                p1[0] = __float2half_rn(v2); p1[SS] = __float2half_rn(v3);
            } else {
                *(uint32_t*)(outp + ((size_t)(bb0 * NHEADS + h) * SS + s0) * HD + dd) = packh2(v0, v1);
                *(uint32_t*)(outp + ((size_t)(bb1 * NHEADS + h) * SS + s1) * HD + dd) = packh2(v2, v3);
            }
        }
    }
}

// ---------------------------------------------------------------------------
// Kernel 2: attention, fp16 m16n8k16, 3 CTAs/SM.
// 128 threads (4 warps), warp tile 32 rows, k-tile 64 keys in four 16-key
// groups. Softmax: mask-select exponent, pack f16x2, h2exp2 -> result IS the
// A-fragment (no shuffles, no extra pack). lr accumulated in f32.
// ---------------------------------------------------------------------------
#define AROWB 144                        // 64 fp16 + pad (%128=16)
#define OFFB_Q  0                        // 128*144 = 18432
#define OFFB_K  18432                    // 2 x 64*144 = 18432
#define OFFB_VT 36864                    // 2 x 64*144 = 18432
#define OFFB_MK 55296                    // 128 ints = 512
#define ATTN_SMEM_BYTES 55808

__global__ void __launch_bounds__(128, 3) attn_kernel(const int* __restrict__ amask,
                                                      float* __restrict__ out)
{
    extern __shared__ char smx[];
    const uint32_t sb = smem_u32(smx);

    const int tid  = threadIdx.x;
    const int wid  = tid >> 5;
    const int lane = tid & 31;
    const int g    = lane >> 2;
    const int t4   = lane & 3;
    const int wm   = wid * 32;

    const uint32_t fr = (uint32_t)(lane & 15) * AROWB + (uint32_t)((lane >> 4) << 4);

    const int bh = blockIdx.x;
    const int b  = bh >> 4;
    const int q0 = blockIdx.y * 128;

    const __half* Qb = g_Q + (size_t)bh * SS * HD;
    const __half* Kb = g_K + (size_t)bh * SS * HD;
    const __half* Vb = g_V + (size_t)bh * HD * SS;   // transposed [d][s]

    // ---- stage Q tile [128x64] fp16 (persistent) ----
    #pragma unroll
    for (int i = 0; i < 8; i++) {
        int idx = tid + i * 128;
        int r = idx >> 3, c8 = idx & 7;
        *(uint4*)(smx + r * AROWB + c8 * 16) =
            *(const uint4*)(Qb + (size_t)(q0 + r) * HD + c8 * 8);
    }

#define ISSUE_TILE(KT, BUF)                                                     \
    {                                                                           \
        const int k0_ = (KT) * 64;                                              \
        const uint32_t kb_ = sb + (uint32_t)(OFFB_K  + (BUF) * 64 * AROWB);     \
        const uint32_t vb_ = sb + (uint32_t)(OFFB_VT + (BUF) * 64 * AROWB);     \
        _Pragma("unroll")                                                       \
        for (int i = 0; i < 4; i++) {                                           \
            int idx = tid + i * 128;                                            \
            int r = idx >> 3, c8 = idx & 7;                                     \
            cp16(kb_ + (uint32_t)(r * AROWB + c8 * 16),                         \
                 Kb + (size_t)(k0_ + r) * HD + c8 * 8);                         \
            cp16(vb_ + (uint32_t)(r * AROWB + c8 * 16),                         \
                 Vb + (size_t)r * SS + k0_ + c8 * 8);                           \
        }                                                                       \
        if (tid < 64)                                                           \
            cp4(sb + (uint32_t)(OFFB_MK + ((BUF) * 64 + tid) * 4),              \
                amask + (size_t)b * SS + k0_ + tid);                            \
        CP_COMMIT();                                                            \
    }

    ISSUE_TILE(0, 0);

    // ---- resident Q fragments: 2 mi x 4 ksteps x 4 regs ----
    __syncthreads();
    uint32_t qf[2][4][4];
    #pragma unroll
    for (int mi = 0; mi < 2; mi++)
        #pragma unroll
        for (int ks = 0; ks < 4; ks++)
            ldsm_x4(qf[mi][ks], sb + fr + (uint32_t)((wm + mi * 16) * AROWB + ks * 32));

    float oacc[2][8][4];
    #pragma unroll
    for (int mi = 0; mi < 2; mi++)
        #pragma unroll
        for (int nj = 0; nj < 8; nj++)
            #pragma unroll
            for (int e = 0; e < 4; e++) oacc[mi][nj][e] = 0.f;
    float lrA[2] = {0.f, 0.f}, lrB[2] = {0.f, 0.f};

    for (int kt = 0; kt < SS / 64; kt++) {
        const int buf = kt & 1;

        CP_WAIT0();
        __syncthreads();
        if (kt + 1 < SS / 64) ISSUE_TILE(kt + 1, buf ^ 1);

        const uint32_t ksb = sb + (uint32_t)(OFFB_K  + buf * 64 * AROWB) + fr;
        const uint32_t vsb = sb + (uint32_t)(OFFB_VT + buf * 64 * AROWB) + fr;
        const int* mki = (const int*)(smx + OFFB_MK) + buf * 64;

        // ---- four independent 16-key groups ----
        #pragma unroll
        for (int p = 0; p < 4; p++) {
            // MMA1: S[32 x 16] for keys [p*16, p*16+16)
            float sg[2][2][4];
            #pragma unroll
            for (int mi = 0; mi < 2; mi++)
                #pragma unroll
                for (int sub = 0; sub < 2; sub++)
                    #pragma unroll
                    for (int e = 0; e < 4; e++) sg[mi][sub][e] = 0.f;

            #pragma unroll
            for (int ks = 0; ks < 4; ks++) {
                uint32_t bq[4];
                ldsm_x4(bq, ksb + (uint32_t)(p * 16 * AROWB + ks * 32));
                #pragma unroll
                for (int mi = 0; mi < 2; mi++) {
                    mma16(sg[mi][0], qf[mi][ks], bq[0], bq[2]);
                    mma16(sg[mi][1], qf[mi][ks], bq[1], bq[3]);
                }
            }

            // softmax: p = 2^(s*SCL2E) masked; result f16x2 == A-frag layout
            uint32_t pa[2][4];
            #pragma unroll
            for (int sub = 0; sub < 2; sub++) {
                const int nj = 2 * p + sub;
                bool m0 = mki[nj * 8 + 2 * t4] != 0;
                bool m1 = mki[nj * 8 + 2 * t4 + 1] != 0;
                #pragma unroll
                for (int mi = 0; mi < 2; mi++) {
                    float t0 = m0 ? sg[mi][sub][0] * SCL2E : -100.f;
                    float t1 = m1 ? sg[mi][sub][1] * SCL2E : -100.f;
                    float t2 = m0 ? sg[mi][sub][2] * SCL2E : -100.f;
                    float t3 = m1 ? sg[mi][sub][3] * SCL2E : -100.f;
                    __half2 e01 = h2exp2(__floats2half2_rn(t0, t1));
                    __half2 e23 = h2exp2(__floats2half2_rn(t2, t3));
                    pa[mi][2 * sub]     = *(uint32_t*)&e01;
                    pa[mi][2 * sub + 1] = *(uint32_t*)&e23;
                    float2 f01 = __half22float2(e01);
                    float2 f23 = __half22float2(e23);
                    lrA[mi] += f01.x + f01.y;
                    lrB[mi] += f23.x + f23.y;
                }
            }

            // MMA2: O += P[32 x 16] V[16 x 64]
            #pragma unroll
            for (int pp = 0; pp < 4; pp++) {
                uint32_t bv[4];
                ldsm_x4(bv, vsb + (uint32_t)(pp * 16 * AROWB + p * 32));
                #pragma unroll
                for (int mi = 0; mi < 2; mi++) {
                    mma16(oacc[mi][2 * pp],     pa[mi], bv[0], bv[2]);
                    mma16(oacc[mi][2 * pp + 1], pa[mi], bv[1], bv[3]);
                }
            }
        }
    }

    // ---- reduce row sums across quad, normalize, store ----
    #pragma unroll
    for (int mi = 0; mi < 2; mi++) {
        lrA[mi] += __shfl_xor_sync(0xFFFFFFFFu, lrA[mi], 1);
        lrA[mi] += __shfl_xor_sync(0xFFFFFFFFu, lrA[mi], 2);
        lrB[mi] += __shfl_xor_sync(0xFFFFFFFFu, lrB[mi], 1);
        lrB[mi] += __shfl_xor_sync(0xFFFFFFFFu, lrB[mi], 2);
    }

    #pragma unroll
    for (int mi = 0; mi < 2; mi++) {
        int r0 = wm + mi * 16 + g;
        int r1 = r0 + 8;
        float il0 = 1.f / lrA[mi];
        float il1 = 1.f / lrB[mi];
        #pragma unroll
        for (int nj = 0; nj < 8; nj++) {
            int c0 = nj * 8 + 2 * t4;
            float* p0 = out + ((size_t)bh * SS + q0 + r0) * HD + c0;
            float* p1 = out + ((size_t)bh * SS + q0 + r1) * HD + c0;
            *(float2*)p0 = make_float2(oacc[mi][nj][0] * il0, oacc[mi][nj][1] * il0);
            *(float2*)p1 = make_float2(oacc[mi][nj][2] * il1, oacc[mi][nj][3] * il1);
        }
    }
}

// ---------------------------------------------------------------------------
extern "C" void kernel_launch(void* const* d_in, const int* in_sizes, int n_in,
                              void* d_out, int out_size)
{
    (void)in_sizes; (void)n_in; (void)out_size;
    const float* q  = (const float*)d_in[0];
    const float* k  = (const float*)d_in[1];
    const float* v  = (const float*)d_in[2];
    const int*   am = (const int*)  d_in[3];
    const float* Wq = (const float*)d_in[4];
    const float* bq = (const float*)d_in[5];
    const float* Wk = (const float*)d_in[6];
    const float* bk = (const float*)d_in[7];
    const float* Wv = (const float*)d_in[8];
    const float* bv = (const float*)d_in[9];

    static int attr_set = 0;
    if (!attr_set) {
        cudaFuncSetAttribute(attn_kernel, cudaFuncAttributeMaxDynamicSharedMemorySize,
                             ATTN_SMEM_BYTES);
        cudaFuncSetAttribute(proj_kernel, cudaFuncAttributeMaxDynamicSharedMemorySize,
                             PROJ_SMEM_BYTES);
        attr_set = 1;
    }

    const int nx8 = MROWS * EMBED / 8;   // 524288
    dim3 cgrid((nx8 + 255) / 256, 6);
    cvt_all_kernel<<<cgrid, 256>>>(q, k, v, Wq, Wk, Wv);

    dim3 pgrid(EMBED / 128, MROWS / 128, 3);   // (8, 32, 3)
    proj_kernel<<<pgrid, 256, PROJ_SMEM_BYTES>>>(bq, bk, bv);

    dim3 agrid(BHD, SS / 128);                 // (32, 16)
    attn_kernel<<<agrid, 128, ATTN_SMEM_BYTES>>>(am, (float*)d_out);
}

// round 17
// speedup vs baseline: 2.7953x; 1.0487x over previous
#include <cuda_runtime.h>
#include <cuda_fp16.h>
#include <cstdint>
#include <math.h>

#define EMBED 1024
#define NHEADS 16
#define HD 64
#define BB 2
#define SS 2048
#define BHD (BB*NHEADS)   // 32
#define MROWS (BB*SS)     // 4096
#define SCALE 0.03125f    // 1/sqrt(1024)
#define SCL2E 0.0450844f  // SCALE * log2(e)
#define NSPLIT 4
#define TILES_PER_SPLIT (SS / 64 / NSPLIT)   // 8

// fp16 copies of inputs
__device__ __half g_Xh[3][(size_t)MROWS*EMBED];
__device__ __half g_Wh[3][(size_t)EMBED*EMBED];
// Projected Q,K in [B,H,S,D]; V TRANSPOSED as [B,H,D,S]. All fp16.
__device__ __half g_Q[(size_t)BB*NHEADS*SS*HD];
__device__ __half g_K[(size_t)BB*NHEADS*SS*HD];
__device__ __half g_V[(size_t)BB*NHEADS*SS*HD];
// Split-K partials: unnormalized O and row sums l, per split
__device__ float g_Opart[(size_t)NSPLIT*BHD*SS*HD];   // 64 MB
__device__ float g_Lpart[(size_t)NSPLIT*BHD*SS];      // 1 MB

__device__ __forceinline__ uint32_t smem_u32(const void* p) {
    uint32_t a;
    asm("{ .reg .u64 t; cvta.to.shared.u64 t, %1; cvt.u32.u64 %0, t; }" : "=r"(a) : "l"(p));
    return a;
}

__device__ __forceinline__ uint32_t packh2(float lo, float hi) {
    __half2 h = __floats2half2_rn(lo, hi);
    return *(uint32_t*)&h;
}

// D = A(16x16 f16) * B(16x8 f16) + D, f32 accum. row.col.
__device__ __forceinline__ void mma16(float* d, const uint32_t* a, uint32_t b0, uint32_t b1) {
    asm volatile(
        "mma.sync.aligned.m16n8k16.row.col.f32.f16.f16.f32 "
        "{%0,%1,%2,%3}, {%4,%5,%6,%7}, {%8,%9}, {%0,%1,%2,%3};"
        : "+f"(d[0]), "+f"(d[1]), "+f"(d[2]), "+f"(d[3])
        : "r"(a[0]), "r"(a[1]), "r"(a[2]), "r"(a[3]), "r"(b0), "r"(b1));
}

// ldmatrix x4 of b16 (fp16) data
__device__ __forceinline__ void ldsm_x4(uint32_t* r, uint32_t addr) {
    asm volatile("ldmatrix.sync.aligned.m8n8.x4.shared.b16 {%0,%1,%2,%3}, [%4];"
        : "=r"(r[0]), "=r"(r[1]), "=r"(r[2]), "=r"(r[3]) : "r"(addr));
}

// cp.async helpers
__device__ __forceinline__ void cp16(uint32_t dst, const void* src) {
    asm volatile("cp.async.cg.shared.global [%0], [%1], 16;" :: "r"(dst), "l"(src));
}
__device__ __forceinline__ void cp4(uint32_t dst, const void* src) {
    asm volatile("cp.async.ca.shared.global [%0], [%1], 4;" :: "r"(dst), "l"(src));
}
#define CP_COMMIT() asm volatile("cp.async.commit_group;" ::: "memory")
#define CP_WAIT0()  asm volatile("cp.async.wait_group 0;" ::: "memory")

// ---------------------------------------------------------------------------
// Kernel 0: fused f32 -> fp16 conversion of all 6 input arrays
// ---------------------------------------------------------------------------
__global__ void __launch_bounds__(256) cvt_all_kernel(
    const float* __restrict__ s0, const float* __restrict__ s1, const float* __restrict__ s2,
    const float* __restrict__ s3, const float* __restrict__ s4, const float* __restrict__ s5)
{
    const int z = blockIdx.y;
    const int nx8 = MROWS * EMBED / 8;
    const int nw8 = EMBED * EMBED / 8;
    const int n8 = (z < 3) ? nx8 : nw8;
    int i = blockIdx.x * 256 + threadIdx.x;
    if (i >= n8) return;
    const float* src = (z == 0) ? s0 : (z == 1) ? s1 : (z == 2) ? s2
                     : (z == 3) ? s3 : (z == 4) ? s4 : s5;
    __half* dst = (z < 3) ? g_Xh[z] : g_Wh[z - 3];
    const float4* sp = ((const float4*)src) + (size_t)i * 2;
    float4 v0 = sp[0], v1 = sp[1];
    uint4 o;
    o.x = packh2(v0.x, v0.y);
    o.y = packh2(v0.z, v0.w);
    o.z = packh2(v1.x, v1.y);
    o.w = packh2(v1.z, v1.w);
    ((uint4*)dst)[i] = o;
}

// ---------------------------------------------------------------------------
// Kernel 1: QKV projection  y = fp16(x @ W^T + b)
// Q,K -> [B,H,S,D];  V -> [B,H,D,S] (transposed).
// BM=BN=128, BK=64 (fp16). 8 warps as 2x4, warp tile 64x32, m16n8k16.
// cp.async double-buffered staging, 1 barrier/chunk (16 chunks).
// ---------------------------------------------------------------------------
#define PROWB 144          // smem row bytes: 64 fp16 + 8 pad (%128=16 -> ldsm ok)
#define PBUFB (128*PROWB)  // one operand tile = 18432 B
#define PROJ_SMEM_BYTES (4 * PBUFB)   // A+B x 2 buffers = 73728

__global__ void __launch_bounds__(256, 2) proj_kernel(
    const float* __restrict__ bq, const float* __restrict__ bk, const float* __restrict__ bv)
{
    extern __shared__ char psm[];
    const uint32_t base = smem_u32(psm);

    const int z = blockIdx.z;
    const __half* x = g_Xh[z];
    const __half* W = g_Wh[z];
    const float* bias = (z == 0) ? bq : (z == 1) ? bk : bv;
    __half* outp = (z == 0) ? g_Q : (z == 1) ? g_K : g_V;

    const int m0 = blockIdx.y * 128;
    const int n0 = blockIdx.x * 128;
    const int tid  = threadIdx.x;
    const int lane = tid & 31;
    const int wid  = tid >> 5;
    const int g    = lane >> 2;
    const int t4   = lane & 3;
    const int wm   = (wid >> 2) * 64;
    const int wn   = (wid & 3) * 32;

    const uint32_t fr = (uint32_t)(lane & 15) * PROWB + (uint32_t)((lane >> 4) << 4);

#define PROJ_ISSUE(C, BUF)                                                      \
    {                                                                           \
        const int k0_ = (C) * 64;                                               \
        const uint32_t ab_ = base + (uint32_t)((BUF) * 2 * PBUFB);              \
        const uint32_t bb_ = ab_ + PBUFB;                                       \
        _Pragma("unroll")                                                       \
        for (int i = 0; i < 4; i++) {                                           \
            int idx = tid + i * 256;                                            \
            int r = idx >> 3, c8 = idx & 7;                                     \
            cp16(ab_ + (uint32_t)(r * PROWB + c8 * 16),                         \
                 x + (size_t)(m0 + r) * EMBED + k0_ + c8 * 8);                  \
            cp16(bb_ + (uint32_t)(r * PROWB + c8 * 16),                         \
                 W + (size_t)(n0 + r) * EMBED + k0_ + c8 * 8);                  \
        }                                                                       \
        CP_COMMIT();                                                            \
    }

    float acc[4][4][4];
    #pragma unroll
    for (int mi = 0; mi < 4; mi++)
        #pragma unroll
        for (int nj = 0; nj < 4; nj++)
            #pragma unroll
            for (int e = 0; e < 4; e++) acc[mi][nj][e] = 0.f;

    PROJ_ISSUE(0, 0);

    for (int c = 0; c < EMBED / 64; c++) {
        const int buf = c & 1;
        CP_WAIT0();
        __syncthreads();
        if (c + 1 < EMBED / 64) PROJ_ISSUE(c + 1, buf ^ 1);

        const uint32_t asb = base + (uint32_t)(buf * 2 * PBUFB) + fr;
        const uint32_t bsb = asb + PBUFB;
        #pragma unroll
        for (int ks = 0; ks < 4; ks++) {
            uint32_t af[4][4], bf[2][4];
            #pragma unroll
            for (int mi = 0; mi < 4; mi++)
                ldsm_x4(af[mi], asb + (uint32_t)((wm + mi * 16) * PROWB + ks * 32));
            #pragma unroll
            for (int pb = 0; pb < 2; pb++)
                ldsm_x4(bf[pb], bsb + (uint32_t)((wn + pb * 16) * PROWB + ks * 32));
            #pragma unroll
            for (int mi = 0; mi < 4; mi++)
                #pragma unroll
                for (int pb = 0; pb < 2; pb++) {
                    mma16(acc[mi][2 * pb],     af[mi], bf[pb][0], bf[pb][2]);
                    mma16(acc[mi][2 * pb + 1], af[mi], bf[pb][1], bf[pb][3]);
                }
        }
    }

    // epilogue: +bias, fp16-round, scatter
    #pragma unroll
    for (int mi = 0; mi < 4; mi++) {
        int r0 = m0 + wm + mi * 16 + g;
        int r1 = r0 + 8;
        int bb0 = r0 >> 11, s0 = r0 & 2047;
        int bb1 = r1 >> 11, s1 = r1 & 2047;
        #pragma unroll
        for (int nj = 0; nj < 4; nj++) {
            int f = n0 + wn + nj * 8 + 2 * t4;
            int h = f >> 6, dd = f & 63;
            float b0 = bias[f], b1 = bias[f + 1];
            float v0 = acc[mi][nj][0] + b0;
            float v1 = acc[mi][nj][1] + b1;
            float v2 = acc[mi][nj][2] + b0;
            float v3 = acc[mi][nj][3] + b1;
            if (z == 2) {
                // V transposed: [B,H,D,S]
                __half* p0 = outp + ((size_t)(bb0 * NHEADS + h) * HD + dd) * SS + s0;
                __half* p1 = outp + ((size_t)(bb1 * NHEADS + h) * HD + dd) * SS + s1;
                p0[0] = __float2half_rn(v0); p0[SS] = __float2half_rn(v1);
                p1[0] = __float2half_rn(v2); p1[SS] = __float2half_rn(v3);
            } else {
                *(uint32_t*)(outp + ((size_t)(bb0 * NHEADS + h) * SS + s0) * HD + dd) = packh2(v0, v1);
                *(uint32_t*)(outp + ((size_t)(bb1 * NHEADS + h) * SS + s1) * HD + dd) = packh2(v2, v3);
            }
        }
    }
}

// ---------------------------------------------------------------------------
// Kernel 2: attention, fp16 m16n8k16, 3 CTAs/SM, SPLIT-K over keys (x4).
// Each CTA: (bh, 128 q-rows, 8 of 32 k-tiles) -> unnormalized partial O + l.
// 128 threads (4 warps), warp tile 32 rows, k-tile 64 keys in 16-key groups.
// Softmax via h2exp2 producing A-fragments directly. Double-buffered cp.async.
// ---------------------------------------------------------------------------
#define AROWB 144                        // 64 fp16 + pad (%128=16)
#define OFFB_Q  0                        // 128*144 = 18432
#define OFFB_K  18432                    // 2 x 64*144 = 18432
#define OFFB_VT 36864                    // 2 x 64*144 = 18432
#define OFFB_MK 55296                    // 128 ints = 512
#define ATTN_SMEM_BYTES 55808

__global__ void __launch_bounds__(128, 3) attn_kernel(const int* __restrict__ amask)
{
    extern __shared__ char smx[];
    const uint32_t sb = smem_u32(smx);

    const int tid  = threadIdx.x;
    const int wid  = tid >> 5;
    const int lane = tid & 31;
    const int g    = lane >> 2;
    const int t4   = lane & 3;
    const int wm   = wid * 32;

    const uint32_t fr = (uint32_t)(lane & 15) * AROWB + (uint32_t)((lane >> 4) << 4);

    const int bh = blockIdx.x;
    const int b  = bh >> 4;
    const int q0 = blockIdx.y * 128;
    const int sp = blockIdx.z;
    const int kt0 = sp * TILES_PER_SPLIT;

    const __half* Qb = g_Q + (size_t)bh * SS * HD;
    const __half* Kb = g_K + (size_t)bh * SS * HD;
    const __half* Vb = g_V + (size_t)bh * HD * SS;   // transposed [d][s]

    // ---- stage Q tile [128x64] fp16 (persistent) ----
    #pragma unroll
    for (int i = 0; i < 8; i++) {
        int idx = tid + i * 128;
        int r = idx >> 3, c8 = idx & 7;
        *(uint4*)(smx + r * AROWB + c8 * 16) =
            *(const uint4*)(Qb + (size_t)(q0 + r) * HD + c8 * 8);
    }

#define ISSUE_TILE(KT, BUF)                                                     \
    {                                                                           \
        const int k0_ = (KT) * 64;                                              \
        const uint32_t kb_ = sb + (uint32_t)(OFFB_K  + (BUF) * 64 * AROWB);     \
        const uint32_t vb_ = sb + (uint32_t)(OFFB_VT + (BUF) * 64 * AROWB);     \
        _Pragma("unroll")                                                       \
        for (int i = 0; i < 4; i++) {                                           \
            int idx = tid + i * 128;                                            \
            int r = idx >> 3, c8 = idx & 7;                                     \
            cp16(kb_ + (uint32_t)(r * AROWB + c8 * 16),                         \
                 Kb + (size_t)(k0_ + r) * HD + c8 * 8);                         \
            cp16(vb_ + (uint32_t)(r * AROWB + c8 * 16),                         \
                 Vb + (size_t)r * SS + k0_ + c8 * 8);                           \
        }                                                                       \
        if (tid < 64)                                                           \
            cp4(sb + (uint32_t)(OFFB_MK + ((BUF) * 64 + tid) * 4),              \
                amask + (size_t)b * SS + k0_ + tid);                            \
        CP_COMMIT();                                                            \
    }

    ISSUE_TILE(kt0, 0);

    // ---- resident Q fragments: 2 mi x 4 ksteps x 4 regs ----
    __syncthreads();
    uint32_t qf[2][4][4];
    #pragma unroll
    for (int mi = 0; mi < 2; mi++)
        #pragma unroll
        for (int ks = 0; ks < 4; ks++)
            ldsm_x4(qf[mi][ks], sb + fr + (uint32_t)((wm + mi * 16) * AROWB + ks * 32));

    float oacc[2][8][4];
    #pragma unroll
    for (int mi = 0; mi < 2; mi++)
        #pragma unroll
        for (int nj = 0; nj < 8; nj++)
            #pragma unroll
            for (int e = 0; e < 4; e++) oacc[mi][nj][e] = 0.f;
    float lrA[2] = {0.f, 0.f}, lrB[2] = {0.f, 0.f};

    for (int t = 0; t < TILES_PER_SPLIT; t++) {
        const int buf = t & 1;

        CP_WAIT0();
        __syncthreads();
        if (t + 1 < TILES_PER_SPLIT) ISSUE_TILE(kt0 + t + 1, buf ^ 1);

        const uint32_t ksb = sb + (uint32_t)(OFFB_K  + buf * 64 * AROWB) + fr;
        const uint32_t vsb = sb + (uint32_t)(OFFB_VT + buf * 64 * AROWB) + fr;
        const int* mki = (const int*)(smx + OFFB_MK) + buf * 64;

        // ---- four independent 16-key groups ----
        #pragma unroll
        for (int p = 0; p < 4; p++) {
            // MMA1: S[32 x 16] for keys [p*16, p*16+16)
            float sg[2][2][4];
            #pragma unroll
            for (int mi = 0; mi < 2; mi++)
                #pragma unroll
                for (int sub = 0; sub < 2; sub++)
                    #pragma unroll
                    for (int e = 0; e < 4; e++) sg[mi][sub][e] = 0.f;

            #pragma unroll
            for (int ks = 0; ks < 4; ks++) {
                uint32_t bq[4];
                ldsm_x4(bq, ksb + (uint32_t)(p * 16 * AROWB + ks * 32));
                #pragma unroll
                for (int mi = 0; mi < 2; mi++) {
                    mma16(sg[mi][0], qf[mi][ks], bq[0], bq[2]);
                    mma16(sg[mi][1], qf[mi][ks], bq[1], bq[3]);
                }
            }

            // softmax: p = 2^(s*SCL2E) masked; result f16x2 == A-frag layout
            uint32_t pa[2][4];
            #pragma unroll
            for (int sub = 0; sub < 2; sub++) {
                const int nj = 2 * p + sub;
                bool m0 = mki[nj * 8 + 2 * t4] != 0;
                bool m1 = mki[nj * 8 + 2 * t4 + 1] != 0;
                #pragma unroll
                for (int mi = 0; mi < 2; mi++) {
                    float t0 = m0 ? sg[mi][sub][0] * SCL2E : -100.f;
                    float t1 = m1 ? sg[mi][sub][1] * SCL2E : -100.f;
                    float t2 = m0 ? sg[mi][sub][2] * SCL2E : -100.f;
                    float t3 = m1 ? sg[mi][sub][3] * SCL2E : -100.f;
                    __half2 e01 = h2exp2(__floats2half2_rn(t0, t1));
                    __half2 e23 = h2exp2(__floats2half2_rn(t2, t3));
                    pa[mi][2 * sub]     = *(uint32_t*)&e01;
                    pa[mi][2 * sub + 1] = *(uint32_t*)&e23;
                    float2 f01 = __half22float2(e01);
                    float2 f23 = __half22float2(e23);
                    lrA[mi] += f01.x + f01.y;
                    lrB[mi] += f23.x + f23.y;
                }
            }

            // MMA2: O += P[32 x 16] V[16 x 64]
            #pragma unroll
            for (int pp = 0; pp < 4; pp++) {
                uint32_t bv[4];
                ldsm_x4(bv, vsb + (uint32_t)(pp * 16 * AROWB + p * 32));
                #pragma unroll
                for (int mi = 0; mi < 2; mi++) {
                    mma16(oacc[mi][2 * pp],     pa[mi], bv[0], bv[2]);
                    mma16(oacc[mi][2 * pp + 1], pa[mi], bv[1], bv[3]);
                }
            }
        }
    }

    // ---- reduce row sums across quad; write UNNORMALIZED partials ----
    #pragma unroll
    for (int mi = 0; mi < 2; mi++) {
        lrA[mi] += __shfl_xor_sync(0xFFFFFFFFu, lrA[mi], 1);
        lrA[mi] += __shfl_xor_sync(0xFFFFFFFFu, lrA[mi], 2);
        lrB[mi] += __shfl_xor_sync(0xFFFFFFFFu, lrB[mi], 1);
        lrB[mi] += __shfl_xor_sync(0xFFFFFFFFu, lrB[mi], 2);
    }

    float* Op = g_Opart + ((size_t)sp * BHD + bh) * SS * HD + (size_t)q0 * HD;
    float* Lp = g_Lpart + ((size_t)sp * BHD + bh) * SS + q0;
    #pragma unroll
    for (int mi = 0; mi < 2; mi++) {
        int r0 = wm + mi * 16 + g;
        int r1 = r0 + 8;
        if (t4 == 0) { Lp[r0] = lrA[mi]; Lp[r1] = lrB[mi]; }
        #pragma unroll
        for (int nj = 0; nj < 8; nj++) {
            int c0 = nj * 8 + 2 * t4;
            *(float2*)(Op + (size_t)r0 * HD + c0) = make_float2(oacc[mi][nj][0], oacc[mi][nj][1]);
            *(float2*)(Op + (size_t)r1 * HD + c0) = make_float2(oacc[mi][nj][2], oacc[mi][nj][3]);
        }
    }
}

// ---------------------------------------------------------------------------
// Kernel 3: split-K reduction: out = (sum_sp O_sp) / (sum_sp l_sp)
// One thread per float4 of output: 32*2048*16 = 1,048,576 threads.
// ---------------------------------------------------------------------------
__global__ void __launch_bounds__(256) reduce_kernel(float* __restrict__ out)
{
    int gid = blockIdx.x * 256 + threadIdx.x;
    int row = gid >> 4;          // bh*SS + s  (< 65536)
    int d4  = gid & 15;

    float4 acc = make_float4(0.f, 0.f, 0.f, 0.f);
    float l = 0.f;
    #pragma unroll
    for (int sp = 0; sp < NSPLIT; sp++) {
        const float4* o = (const float4*)(g_Opart + (size_t)sp * BHD * SS * HD)
                        + (size_t)row * 16 + d4;
        float4 v = *o;
        acc.x += v.x; acc.y += v.y; acc.z += v.z; acc.w += v.w;
        l += g_Lpart[(size_t)sp * BHD * SS + row];
    }
    float il = 1.f / l;
    acc.x *= il; acc.y *= il; acc.z *= il; acc.w *= il;
    ((float4*)out)[(size_t)row * 16 + d4] = acc;
}

// ---------------------------------------------------------------------------
extern "C" void kernel_launch(void* const* d_in, const int* in_sizes, int n_in,
                              void* d_out, int out_size)
{
    (void)in_sizes; (void)n_in; (void)out_size;
    const float* q  = (const float*)d_in[0];
    const float* k  = (const float*)d_in[1];
    const float* v  = (const float*)d_in[2];
    const int*   am = (const int*)  d_in[3];
    const float* Wq = (const float*)d_in[4];
    const float* bq = (const float*)d_in[5];
    const float* Wk = (const float*)d_in[6];
    const float* bk = (const float*)d_in[7];
    const float* Wv = (const float*)d_in[8];
    const float* bv = (const float*)d_in[9];

    static int attr_set = 0;
    if (!attr_set) {
        cudaFuncSetAttribute(attn_kernel, cudaFuncAttributeMaxDynamicSharedMemorySize,
                             ATTN_SMEM_BYTES);
        cudaFuncSetAttribute(proj_kernel, cudaFuncAttributeMaxDynamicSharedMemorySize,
                             PROJ_SMEM_BYTES);
        attr_set = 1;
    }

    const int nx8 = MROWS * EMBED / 8;   // 524288
    dim3 cgrid((nx8 + 255) / 256, 6);
    cvt_all_kernel<<<cgrid, 256>>>(q, k, v, Wq, Wk, Wv);

    dim3 pgrid(EMBED / 128, MROWS / 128, 3);   // (8, 32, 3)
    proj_kernel<<<pgrid, 256, PROJ_SMEM_BYTES>>>(bq, bk, bv);

    dim3 agrid(BHD, SS / 128, NSPLIT);         // (32, 16, 4)
    attn_kernel<<<agrid, 128, ATTN_SMEM_BYTES>>>(am);

    reduce_kernel<<<(BHD * SS * (HD / 4)) / 256, 256>>>((float*)d_out);
}